// round 1
// baseline (speedup 1.0000x reference)
#include <cuda_runtime.h>
#include <math.h>
#include <cstdint>

#define BB 16
#define CC 512
#define SS 4096
#define HH 8
#define DD 64
#define QKV 1536

// Scratch (static __device__ — allocation-free per harness rules)
__device__ float g_r[BB * SS];                       // 256 KB  input rms scale (incl sqrt(512))
__device__ float g_qkv[(size_t)BB * QKV * SS];       // 403 MB  qkv activations
__device__ float g_kmax[BB * 512];                   // k row max
__device__ float g_ksum[BB * 512];                   // k row sumexp
__device__ float g_ctx[BB * HH * DD * DD];           // 2 MB    context matrices
__device__ float g_mid[(size_t)BB * CC * SS];        // 134 MB  attention output (pre-proj)

// ---------------------------------------------------------------------------
// K0: r[b,s] = sqrt(512) / max(||x[b,:,s]||, eps)
// ---------------------------------------------------------------------------
__global__ void k_rnorm_in(const float* __restrict__ x) {
    int idx = blockIdx.x * 256 + threadIdx.x;      // b*S + s
    int b = idx >> 12, s = idx & (SS - 1);
    const float* p = x + (size_t)b * CC * SS + s;
    float acc = 0.f;
#pragma unroll 8
    for (int c = 0; c < CC; c++) { float v = p[(size_t)c * SS]; acc += v * v; }
    g_r[idx] = 22.62741699796952f / fmaxf(sqrtf(acc), 1e-12f);
}

// ---------------------------------------------------------------------------
// Tiled SGEMM: C[b] = A[M,K] @ Bsrc[b][K,N]  (A row-major, shared over batch)
//   GK: multiply B rows by gk[k] (gamma1) at load
//   CS: multiply output columns by cs[b*N + n] (rms scale)
//   BI: add bias[m]
// BM=BN=128, BK=16, 256 threads, 8x8 per thread, 2 CTAs/SM.
// ---------------------------------------------------------------------------
template <bool GK, bool CS, bool BI>
__global__ __launch_bounds__(256, 2)
void k_gemm(const float* __restrict__ A, const float* __restrict__ Bg,
            float* __restrict__ Cg, const float* __restrict__ gk,
            const float* __restrict__ cs, const float* __restrict__ bias,
            int M, int N, int K, size_t bStrideB, size_t bStrideC) {
    __shared__ float As[16][132];   // [k][m], padded
    __shared__ float Bs[16][128];   // [k][n]

    int b = blockIdx.z;
    const float* Bsrc = Bg + (size_t)b * bStrideB;
    float* Cdst = Cg + (size_t)b * bStrideC;
    int m0 = blockIdx.y * 128, n0 = blockIdx.x * 128;
    int tid = threadIdx.x;
    int tm = (tid >> 4) * 8, tn = (tid & 15) * 8;

    float acc[8][8] = {};

    for (int k0 = 0; k0 < K; k0 += 16) {
        // A tile: 128x16 -> As[k][m] (transposed)
#pragma unroll
        for (int it = 0; it < 2; it++) {
            int f = tid * 2 + it;                 // 0..511 float4s
            int ml = f >> 2, kq = (f & 3) * 4;
            float4 v = *(const float4*)(A + (size_t)(m0 + ml) * K + k0 + kq);
            As[kq + 0][ml] = v.x; As[kq + 1][ml] = v.y;
            As[kq + 2][ml] = v.z; As[kq + 3][ml] = v.w;
        }
        // B tile: 16x128 -> Bs[k][n]
#pragma unroll
        for (int it = 0; it < 2; it++) {
            int f = tid * 2 + it;
            int kl = f >> 5, nq = (f & 31) * 4;
            float4 v = *(const float4*)(Bsrc + (size_t)(k0 + kl) * N + n0 + nq);
            if (GK) { float g = gk[k0 + kl]; v.x *= g; v.y *= g; v.z *= g; v.w *= g; }
            *(float4*)&Bs[kl][nq] = v;
        }
        __syncthreads();
#pragma unroll
        for (int kk = 0; kk < 16; kk++) {
            float a[8], bv[8];
            *(float4*)(a)     = *(const float4*)&As[kk][tm];
            *(float4*)(a + 4) = *(const float4*)&As[kk][tm + 4];
            *(float4*)(bv)     = *(const float4*)&Bs[kk][tn];
            *(float4*)(bv + 4) = *(const float4*)&Bs[kk][tn + 4];
#pragma unroll
            for (int i = 0; i < 8; i++)
#pragma unroll
                for (int j = 0; j < 8; j++) acc[i][j] += a[i] * bv[j];
        }
        __syncthreads();
    }

    float csv[8];
    if (CS) {
#pragma unroll
        for (int j = 0; j < 8; j++) csv[j] = cs[(size_t)b * N + n0 + tn + j];
    }
#pragma unroll
    for (int i = 0; i < 8; i++) {
        float bi = BI ? bias[m0 + tm + i] : 0.f;
        float o[8];
#pragma unroll
        for (int j = 0; j < 8; j++) {
            float v = acc[i][j];
            if (CS) v *= csv[j];
            if (BI) v += bi;
            o[j] = v;
        }
        float* cp = Cdst + (size_t)(m0 + tm + i) * N + n0 + tn;
        *(float4*)(cp)     = *(float4*)(o);
        *(float4*)(cp + 4) = *(float4*)(o + 4);
    }
}

// ---------------------------------------------------------------------------
// K2: per-row (over n) max & sumexp for k   rows = b*512 + (h*64+d)
// ---------------------------------------------------------------------------
__global__ void k_kstats() {
    int row = blockIdx.x;
    int b = row >> 9, o = row & 511;
    const float* p = g_qkv + ((size_t)b * QKV + 512 + o) * SS;
    __shared__ float red[256];
    int t = threadIdx.x;

    float mx = -3.402823466e38f;
    for (int i = t; i < SS; i += 256) mx = fmaxf(mx, p[i]);
    red[t] = mx; __syncthreads();
    for (int st = 128; st > 0; st >>= 1) {
        if (t < st) red[t] = fmaxf(red[t], red[t + st]);
        __syncthreads();
    }
    mx = red[0]; __syncthreads();

    float sm = 0.f;
    for (int i = t; i < SS; i += 256) sm += expf(p[i] - mx);
    red[t] = sm; __syncthreads();
    for (int st = 128; st > 0; st >>= 1) {
        if (t < st) red[t] += red[t + st];
        __syncthreads();
    }
    if (t == 0) { g_kmax[row] = mx; g_ksum[row] = red[0]; }
}

// ---------------------------------------------------------------------------
// K3: ctx[b,h,d,e] = sum_n softmax_n(k)[d,n] * v[e,n]
// one CTA per (b,h); 256 threads as 16x16, 4x4 each; n chunks of 64
// ---------------------------------------------------------------------------
__global__ __launch_bounds__(256, 1)
void k_context() {
    int h = blockIdx.x, b = blockIdx.y;
    const float* kp = g_qkv + ((size_t)b * QKV + 512 + h * 64) * SS;
    const float* vp = g_qkv + ((size_t)b * QKV + 1024 + h * 64) * SS;

    __shared__ float ks[64][68];   // [n][d] transposed, padded for alignment
    __shared__ float vs[64][68];
    __shared__ float mx_s[64], is_s[64];

    int tid = threadIdx.x;
    if (tid < 64) {
        int base = b * 512 + h * 64 + tid;
        mx_s[tid] = g_kmax[base];
        is_s[tid] = 1.f / g_ksum[base];
    }
    __syncthreads();

    int td = (tid >> 4) * 4, te = (tid & 15) * 4;
    float acc[4][4] = {};

    for (int n0 = 0; n0 < SS; n0 += 64) {
        __syncthreads();
#pragma unroll
        for (int it = 0; it < 4; it++) {
            int f = it * 256 + tid;               // 0..1023 float4s, coalesced
            int dr = f >> 4, nl = (f & 15) * 4;
            float m = mx_s[dr], s = is_s[dr];
            float4 kv = *(const float4*)(kp + (size_t)dr * SS + n0 + nl);
            ks[nl + 0][dr] = expf(kv.x - m) * s;
            ks[nl + 1][dr] = expf(kv.y - m) * s;
            ks[nl + 2][dr] = expf(kv.z - m) * s;
            ks[nl + 3][dr] = expf(kv.w - m) * s;
            float4 vv = *(const float4*)(vp + (size_t)dr * SS + n0 + nl);
            vs[nl + 0][dr] = vv.x; vs[nl + 1][dr] = vv.y;
            vs[nl + 2][dr] = vv.z; vs[nl + 3][dr] = vv.w;
        }
        __syncthreads();
#pragma unroll 4
        for (int nn = 0; nn < 64; nn++) {
            float a[4], bv[4];
            *(float4*)a  = *(const float4*)&ks[nn][td];
            *(float4*)bv = *(const float4*)&vs[nn][te];
#pragma unroll
            for (int i = 0; i < 4; i++)
#pragma unroll
                for (int j = 0; j < 4; j++) acc[i][j] += a[i] * bv[j];
        }
    }

    float* cp = g_ctx + (size_t)(b * HH + h) * DD * DD;
#pragma unroll
    for (int i = 0; i < 4; i++)
        *(float4*)&cp[(td + i) * 64 + te] = *(float4*)acc[i];
}

// ---------------------------------------------------------------------------
// K4: mid[b, h*64+e, n] = sum_d ctx[d,e] * softmax_d(q)[d,n] * D^-0.5
// one thread per n-column; ctx in SMEM (broadcast reads)
// ---------------------------------------------------------------------------
__global__ __launch_bounds__(256, 1)
void k_applyq() {
    int b = blockIdx.z, h = blockIdx.y;
    int n = blockIdx.x * 256 + threadIdx.x;

    __shared__ float cs[64][64];
    const float* ctxp = g_ctx + (size_t)(b * HH + h) * DD * DD;
    for (int i = threadIdx.x; i < 4096; i += 256) ((float*)cs)[i] = ctxp[i];
    __syncthreads();

    const float* qp = g_qkv + ((size_t)b * QKV + h * 64) * SS + n;
    float p[64];
    float mx = -3.402823466e38f;
#pragma unroll
    for (int d = 0; d < 64; d++) { p[d] = qp[(size_t)d * SS]; mx = fmaxf(mx, p[d]); }
    float sm = 0.f;
#pragma unroll
    for (int d = 0; d < 64; d++) { p[d] = expf(p[d] - mx); sm += p[d]; }
    float sc = 0.125f / sm;                        // D^-0.5 / sumexp

    float acc[64] = {};
#pragma unroll 4
    for (int d = 0; d < 64; d++) {
        float pv = p[d] * sc;
#pragma unroll
        for (int e = 0; e < 64; e += 4) {
            float4 c4 = *(const float4*)&cs[d][e];
            acc[e + 0] += c4.x * pv; acc[e + 1] += c4.y * pv;
            acc[e + 2] += c4.z * pv; acc[e + 3] += c4.w * pv;
        }
    }
    float* op = g_mid + ((size_t)b * CC + h * 64) * SS + n;
#pragma unroll
    for (int e = 0; e < 64; e++) op[(size_t)e * SS] = acc[e];
}

// ---------------------------------------------------------------------------
// K6: in-place final rms-norm on d_out
// ---------------------------------------------------------------------------
__global__ void k_rnorm_out(float* __restrict__ y, const float* __restrict__ gamma2) {
    int idx = blockIdx.x * 256 + threadIdx.x;
    int b = idx >> 12, s = idx & (SS - 1);
    float* p = y + (size_t)b * CC * SS + s;
    float acc = 0.f;
#pragma unroll 8
    for (int c = 0; c < CC; c++) { float v = p[(size_t)c * SS]; acc += v * v; }
    float sc = 22.62741699796952f / fmaxf(sqrtf(acc), 1e-12f);
#pragma unroll 8
    for (int c = 0; c < CC; c++) p[(size_t)c * SS] *= sc * gamma2[c];
}

// ---------------------------------------------------------------------------
extern "C" void kernel_launch(void* const* d_in, const int* in_sizes, int n_in,
                              void* d_out, int out_size) {
    const float* x      = (const float*)d_in[0];
    const float* gamma1 = (const float*)d_in[1];
    const float* w_qkv  = (const float*)d_in[2];
    const float* w_out  = (const float*)d_in[3];
    const float* b_out  = (const float*)d_in[4];
    const float* gamma2 = (const float*)d_in[5];
    float* out = (float*)d_out;

    float *qkv_p, *r_p, *mid_p;
    cudaGetSymbolAddress((void**)&qkv_p, g_qkv);
    cudaGetSymbolAddress((void**)&r_p,   g_r);
    cudaGetSymbolAddress((void**)&mid_p, g_mid);

    // K0: input rms scale
    k_rnorm_in<<<BB * SS / 256, 256>>>(x);

    // K1: qkv = (w_qkv * gamma1) @ x, columns scaled by r
    k_gemm<true, true, false><<<dim3(SS / 128, QKV / 128, BB), 256>>>(
        w_qkv, x, qkv_p, gamma1, r_p, nullptr,
        QKV, SS, CC, (size_t)CC * SS, (size_t)QKV * SS);

    // K2: k softmax stats
    k_kstats<<<BB * 512, 256>>>();

    // K3: context matrices
    k_context<<<dim3(HH, BB), 256>>>();

    // K4: apply q-softmax to context
    k_applyq<<<dim3(SS / 256, HH, BB), 256>>>();

    // K5: output projection + bias  -> d_out
    k_gemm<false, false, true><<<dim3(SS / 128, CC / 128, BB), 256>>>(
        w_out, mid_p, out, nullptr, nullptr, b_out,
        CC, SS, CC, (size_t)CC * SS, (size_t)CC * SS);

    // K6: final rms-norm in place
    k_rnorm_out<<<BB * SS / 256, 256>>>(out, gamma2);
}

// round 3
// speedup vs baseline: 3.7805x; 3.7805x over previous
#include <cuda_runtime.h>
#include <math.h>
#include <cstdint>

#define BB 16
#define CC 512
#define SS 4096
#define HH 8
#define DD 64
#define QKV 1536
#define NSPLIT 8
#define NSTG 3

// ---------------- scratch (static __device__, allocation-free) ----------------
__device__ float g_r[BB * SS];
__device__ float g_wq[QKV * CC];                      // w_qkv * gamma1, tf32-rounded
__device__ float g_wo[CC * CC];                       // w_out, tf32-rounded
__device__ float g_xt[(size_t)BB * SS * CC];          // 256 MB  x^T [b][s][c], tf32
__device__ float g_qkv[(size_t)BB * QKV * SS];        // 403 MB
__device__ float g_kmax[BB * 512];
__device__ float g_ksum[BB * 512];
__device__ float g_ctxp[NSPLIT][BB * HH * DD * DD];
__device__ float g_ctx[BB * HH * DD * DD];
__device__ float g_midT[(size_t)BB * SS * CC];        // 134 MB  [b][n][c], tf32

// ---------------- helpers ----------------
__device__ __forceinline__ float tf32r(float x) {
    uint32_t u;
    asm("cvt.rna.tf32.f32 %0, %1;" : "=r"(u) : "f"(x));
    return __uint_as_float(u);
}
__device__ __forceinline__ uint32_t smem_u32(const void* p) {
    uint32_t a;
    asm("{ .reg .u64 t; cvta.to.shared.u64 t, %1; cvt.u32.u64 %0, t; }" : "=r"(a) : "l"(p));
    return a;
}
#define CP_ASYNC(dst, src) \
    asm volatile("cp.async.cg.shared.global [%0], [%1], 16;" :: "r"(dst), "l"(src) : "memory")
#define CP_COMMIT() asm volatile("cp.async.commit_group;" ::: "memory")
#define CP_WAIT(n)  asm volatile("cp.async.wait_group %0;" :: "n"(n) : "memory")

__device__ __forceinline__ void mma8(float* c, const uint32_t* a, const uint32_t* b) {
    asm volatile(
        "mma.sync.aligned.m16n8k8.row.col.f32.tf32.tf32.f32 "
        "{%0,%1,%2,%3},{%4,%5,%6,%7},{%8,%9},{%0,%1,%2,%3};"
        : "+f"(c[0]), "+f"(c[1]), "+f"(c[2]), "+f"(c[3])
        : "r"(a[0]), "r"(a[1]), "r"(a[2]), "r"(a[3]), "r"(b[0]), "r"(b[1]));
}

// ---------------------------------------------------------------------------
// prep: weights -> tf32 scratch (gamma1 folded into w_qkv)
// ---------------------------------------------------------------------------
__global__ void k_prep_wq(const float* __restrict__ w, const float* __restrict__ g1) {
    int i = blockIdx.x * 256 + threadIdx.x;
    g_wq[i] = tf32r(w[i] * g1[i & (CC - 1)]);
}
__global__ void k_prep_wo(const float* __restrict__ w) {
    int i = blockIdx.x * 256 + threadIdx.x;
    g_wo[i] = tf32r(w[i]);
}

// ---------------------------------------------------------------------------
// T: x[b][c][s] -> xt[b][s][c]   (tf32-rounded)
// ---------------------------------------------------------------------------
__global__ void k_transpose(const float* __restrict__ x) {
    __shared__ float t[32][33];
    int b = blockIdx.z, c0 = blockIdx.y * 32, s0 = blockIdx.x * 32;
    int tx = threadIdx.x, ty = threadIdx.y;            // 32 x 8
    const float* xp = x + (size_t)b * CC * SS;
    float* xtp = g_xt + (size_t)b * SS * CC;
#pragma unroll
    for (int i = 0; i < 32; i += 8)
        t[ty + i][tx] = xp[(size_t)(c0 + ty + i) * SS + s0 + tx];
    __syncthreads();
#pragma unroll
    for (int i = 0; i < 32; i += 8)
        xtp[(size_t)(s0 + ty + i) * CC + c0 + tx] = tf32r(t[tx][ty + i]);
}

// ---------------------------------------------------------------------------
// K0: r[b,s] = sqrt(512)/max(||xt[b,s,:]||, eps)   (one warp per row)
// ---------------------------------------------------------------------------
__global__ void k_rnorm_in() {
    int gw = (blockIdx.x * 256 + threadIdx.x) >> 5;
    int lane = threadIdx.x & 31;
    const float4* p = (const float4*)(g_xt + (size_t)gw * CC);
    float acc = 0.f;
#pragma unroll
    for (int i = lane; i < 128; i += 32) {
        float4 v = p[i];
        acc += v.x * v.x + v.y * v.y + v.z * v.z + v.w * v.w;
    }
#pragma unroll
    for (int o = 16; o; o >>= 1) acc += __shfl_xor_sync(0xFFFFFFFFu, acc, o);
    if (!lane) g_r[gw] = 22.62741699796952f / fmaxf(sqrtf(acc), 1e-12f);
}

// ---------------------------------------------------------------------------
// tf32 mma.sync GEMM: C[b][M,N] = A[M,K] @ B[b][N,K]^T
// A, B already tf32-rounded. Tile 128x128, BK=32, cp.async 3-stage.
// 8 warps: (wid/4) -> 64-row band, (wid%4) -> 32-col band.
// ---------------------------------------------------------------------------
template <bool CS, bool BI>
__global__ __launch_bounds__(256, 2)
void k_mma_gemm(const float* __restrict__ A, const float* __restrict__ Bg,
                float* __restrict__ Cg, const float* __restrict__ cs,
                const float* __restrict__ bias,
                int M, int Ntot, int K, size_t strB, size_t strC) {
    extern __shared__ float sm[];
    const int TSZ = 128 * 36;
    float* As = sm;                    // NSTG bufs
    float* Bs = sm + NSTG * TSZ;

    int tid = threadIdx.x, lane = tid & 31, wid = tid >> 5;
    int b = blockIdx.z, m0 = blockIdx.y * 128, n0 = blockIdx.x * 128;
    const float* Ab = A + (size_t)m0 * K;
    const float* Bb = Bg + (size_t)b * strB + (size_t)n0 * K;
    uint32_t sA = smem_u32(As), sB = smem_u32(Bs);

    const int NC = K / 32;

    auto issue = [&](int kc, int buf) {
        int k0 = kc * 32;
#pragma unroll
        for (int it = 0; it < 4; it++) {
            int f = it * 256 + tid;
            int row = f >> 3, kq = (f & 7) * 4;
            uint32_t o = (uint32_t)(buf * TSZ + row * 36 + kq) * 4;
            CP_ASYNC(sA + o, Ab + (size_t)row * K + k0 + kq);
            CP_ASYNC(sB + o, Bb + (size_t)row * K + k0 + kq);
        }
    };

#pragma unroll
    for (int s = 0; s < NSTG; s++) { issue(s, s); CP_COMMIT(); }

    int wm = (wid >> 2) * 64, wn = (wid & 3) * 32;
    float acc[4][4][4] = {};

    for (int kc = 0; kc < NC; kc++) {
        CP_WAIT(NSTG - 1);
        __syncthreads();
        const float* Ax = As + (kc % NSTG) * TSZ;
        const float* Bx = Bs + (kc % NSTG) * TSZ;
#pragma unroll
        for (int ks = 0; ks < 4; ks++) {
            int k = ks * 8 + (lane & 3);
            uint32_t a[4][4], bv[4][2];
#pragma unroll
            for (int mi = 0; mi < 4; mi++) {
                int m = wm + mi * 16 + (lane >> 2);
                a[mi][0] = __float_as_uint(Ax[m * 36 + k]);
                a[mi][1] = __float_as_uint(Ax[(m + 8) * 36 + k]);
                a[mi][2] = __float_as_uint(Ax[m * 36 + k + 4]);
                a[mi][3] = __float_as_uint(Ax[(m + 8) * 36 + k + 4]);
            }
#pragma unroll
            for (int ni = 0; ni < 4; ni++) {
                int n = wn + ni * 8 + (lane >> 2);
                bv[ni][0] = __float_as_uint(Bx[n * 36 + k]);
                bv[ni][1] = __float_as_uint(Bx[n * 36 + k + 4]);
            }
#pragma unroll
            for (int mi = 0; mi < 4; mi++)
#pragma unroll
                for (int ni = 0; ni < 4; ni++)
                    mma8(acc[mi][ni], a[mi], bv[ni]);
        }
        __syncthreads();
        if (kc + NSTG < NC) issue(kc + NSTG, kc % NSTG);
        CP_COMMIT();
    }

    float* Cd = Cg + (size_t)b * strC;
#pragma unroll
    for (int mi = 0; mi < 4; mi++) {
        int r0 = m0 + wm + mi * 16 + (lane >> 2);
        float bi0 = BI ? bias[r0] : 0.f;
        float bi1 = BI ? bias[r0 + 8] : 0.f;
#pragma unroll
        for (int ni = 0; ni < 4; ni++) {
            int c = n0 + wn + ni * 8 + 2 * (lane & 3);
            float s0 = 1.f, s1 = 1.f;
            if (CS) {
                s0 = cs[(size_t)b * Ntot + c];
                s1 = cs[(size_t)b * Ntot + c + 1];
            }
            float2 v0 = make_float2(acc[mi][ni][0] * s0 + bi0, acc[mi][ni][1] * s1 + bi0);
            float2 v1 = make_float2(acc[mi][ni][2] * s0 + bi1, acc[mi][ni][3] * s1 + bi1);
            *(float2*)(Cd + (size_t)r0 * Ntot + c) = v0;
            *(float2*)(Cd + (size_t)(r0 + 8) * Ntot + c) = v1;
        }
    }
}

// ---------------------------------------------------------------------------
// K2: per-row (over n) max & sumexp for k
// ---------------------------------------------------------------------------
__global__ void k_kstats() {
    int row = blockIdx.x;
    int b = row >> 9, o = row & 511;
    const float* p = g_qkv + ((size_t)b * QKV + 512 + o) * SS;
    __shared__ float red[256];
    int t = threadIdx.x;
    float mx = -3.402823466e38f;
    for (int i = t; i < SS; i += 256) mx = fmaxf(mx, p[i]);
    red[t] = mx; __syncthreads();
    for (int st = 128; st > 0; st >>= 1) {
        if (t < st) red[t] = fmaxf(red[t], red[t + st]);
        __syncthreads();
    }
    mx = red[0]; __syncthreads();
    float sm = 0.f;
    for (int i = t; i < SS; i += 256) sm += expf(p[i] - mx);
    red[t] = sm; __syncthreads();
    for (int st = 128; st > 0; st >>= 1) {
        if (t < st) red[t] += red[t + st];
        __syncthreads();
    }
    if (t == 0) { g_kmax[row] = mx; g_ksum[row] = red[0]; }
}

// ---------------------------------------------------------------------------
// K3: partial ctx over n-segment; grid (HH, NSPLIT, BB)
// ---------------------------------------------------------------------------
__global__ __launch_bounds__(256, 1)
void k_context_part() {
    int h = blockIdx.x, seg = blockIdx.y, b = blockIdx.z;
    const float* kp = g_qkv + ((size_t)b * QKV + 512 + h * 64) * SS;
    const float* vp = g_qkv + ((size_t)b * QKV + 1024 + h * 64) * SS;

    __shared__ float ks[64][68];
    __shared__ float vs[64][68];
    __shared__ float mx_s[64], is_s[64];

    int tid = threadIdx.x;
    if (tid < 64) {
        int base = b * 512 + h * 64 + tid;
        mx_s[tid] = g_kmax[base];
        is_s[tid] = 1.f / g_ksum[base];
    }
    __syncthreads();

    int td = (tid >> 4) * 4, te = (tid & 15) * 4;
    float acc[4][4] = {};

    int nbeg = seg * (SS / NSPLIT), nend = nbeg + SS / NSPLIT;
    for (int n0 = nbeg; n0 < nend; n0 += 64) {
        __syncthreads();
#pragma unroll
        for (int it = 0; it < 4; it++) {
            int f = it * 256 + tid;
            int dr = f >> 4, nl = (f & 15) * 4;
            float m = mx_s[dr], s = is_s[dr];
            float4 kv = *(const float4*)(kp + (size_t)dr * SS + n0 + nl);
            ks[nl + 0][dr] = expf(kv.x - m) * s;
            ks[nl + 1][dr] = expf(kv.y - m) * s;
            ks[nl + 2][dr] = expf(kv.z - m) * s;
            ks[nl + 3][dr] = expf(kv.w - m) * s;
            float4 vv = *(const float4*)(vp + (size_t)dr * SS + n0 + nl);
            vs[nl + 0][dr] = vv.x; vs[nl + 1][dr] = vv.y;
            vs[nl + 2][dr] = vv.z; vs[nl + 3][dr] = vv.w;
        }
        __syncthreads();
#pragma unroll 4
        for (int nn = 0; nn < 64; nn++) {
            float a[4], bv[4];
            *(float4*)a  = *(const float4*)&ks[nn][td];
            *(float4*)bv = *(const float4*)&vs[nn][te];
#pragma unroll
            for (int i = 0; i < 4; i++)
#pragma unroll
                for (int j = 0; j < 4; j++) acc[i][j] += a[i] * bv[j];
        }
    }
    float* cp = g_ctxp[seg] + (size_t)(b * HH + h) * DD * DD;
#pragma unroll
    for (int i = 0; i < 4; i++)
        *(float4*)&cp[(td + i) * 64 + te] = *(float4*)acc[i];
}

__global__ void k_ctx_reduce() {
    int i = blockIdx.x * 256 + threadIdx.x;
    float s = 0.f;
#pragma unroll
    for (int p = 0; p < NSPLIT; p++) s += g_ctxp[p][i];
    g_ctx[i] = s;
}

// ---------------------------------------------------------------------------
// K4: midT[b, n, h*64+e] = sum_d ctx[d,e] * softmax_d(q)[d,n] * D^-0.5  (tf32)
// ---------------------------------------------------------------------------
__global__ __launch_bounds__(256, 1)
void k_applyq() {
    int b = blockIdx.z, h = blockIdx.y;
    int n = blockIdx.x * 256 + threadIdx.x;

    __shared__ float cs[64][64];
    const float* ctxp = g_ctx + (size_t)(b * HH + h) * DD * DD;
    for (int i = threadIdx.x; i < 4096; i += 256) ((float*)cs)[i] = ctxp[i];
    __syncthreads();

    const float* qp = g_qkv + ((size_t)b * QKV + h * 64) * SS + n;
    float p[64];
    float mx = -3.402823466e38f;
#pragma unroll
    for (int d = 0; d < 64; d++) { p[d] = qp[(size_t)d * SS]; mx = fmaxf(mx, p[d]); }
    float sm = 0.f;
#pragma unroll
    for (int d = 0; d < 64; d++) { p[d] = expf(p[d] - mx); sm += p[d]; }
    float sc = 0.125f / sm;

    float acc[64] = {};
#pragma unroll 4
    for (int d = 0; d < 64; d++) {
        float pv = p[d] * sc;
#pragma unroll
        for (int e = 0; e < 64; e += 4) {
            float4 c4 = *(const float4*)&cs[d][e];
            acc[e + 0] += c4.x * pv; acc[e + 1] += c4.y * pv;
            acc[e + 2] += c4.z * pv; acc[e + 3] += c4.w * pv;
        }
    }
    float* op = g_midT + ((size_t)b * SS + n) * CC + h * 64;
#pragma unroll
    for (int e = 0; e < 64; e += 4)
        *(float4*)(op + e) = make_float4(tf32r(acc[e]), tf32r(acc[e + 1]),
                                         tf32r(acc[e + 2]), tf32r(acc[e + 3]));
}

// ---------------------------------------------------------------------------
// K6: in-place final rms-norm on d_out
// ---------------------------------------------------------------------------
__global__ void k_rnorm_out(float* __restrict__ y, const float* __restrict__ gamma2) {
    int idx = blockIdx.x * 256 + threadIdx.x;
    int b = idx >> 12, s = idx & (SS - 1);
    float* p = y + (size_t)b * CC * SS + s;
    float acc = 0.f;
#pragma unroll 8
    for (int c = 0; c < CC; c++) { float v = p[(size_t)c * SS]; acc += v * v; }
    float sc = 22.62741699796952f / fmaxf(sqrtf(acc), 1e-12f);
#pragma unroll 8
    for (int c = 0; c < CC; c++) p[(size_t)c * SS] *= sc * gamma2[c];
}

// ---------------------------------------------------------------------------
extern "C" void kernel_launch(void* const* d_in, const int* in_sizes, int n_in,
                              void* d_out, int out_size) {
    const float* x      = (const float*)d_in[0];
    const float* gamma1 = (const float*)d_in[1];
    const float* w_qkv  = (const float*)d_in[2];
    const float* w_out  = (const float*)d_in[3];
    const float* b_out  = (const float*)d_in[4];
    const float* gamma2 = (const float*)d_in[5];
    float* out = (float*)d_out;

    float *xt_p, *qkv_p, *r_p, *midT_p, *wq_p, *wo_p;
    cudaGetSymbolAddress((void**)&xt_p,   g_xt);
    cudaGetSymbolAddress((void**)&qkv_p,  g_qkv);
    cudaGetSymbolAddress((void**)&r_p,    g_r);
    cudaGetSymbolAddress((void**)&midT_p, g_midT);
    cudaGetSymbolAddress((void**)&wq_p,   g_wq);
    cudaGetSymbolAddress((void**)&wo_p,   g_wo);

    const int SMEM_GEMM = NSTG * 2 * 128 * 36 * 4;     // 110592 B
    cudaFuncSetAttribute(k_mma_gemm<true, false>,
                         cudaFuncAttributeMaxDynamicSharedMemorySize, SMEM_GEMM);
    cudaFuncSetAttribute(k_mma_gemm<false, true>,
                         cudaFuncAttributeMaxDynamicSharedMemorySize, SMEM_GEMM);

    // prep weights (tf32, gamma folded)
    k_prep_wq<<<QKV * CC / 256, 256>>>(w_qkv, gamma1);
    k_prep_wo<<<CC * CC / 256, 256>>>(w_out);
    // T: transpose x -> xt (tf32)
    k_transpose<<<dim3(SS / 32, CC / 32, BB), dim3(32, 8)>>>(x);
    // K0: rms scales
    k_rnorm_in<<<BB * SS / 8, 256>>>();
    // K1: qkv = wq @ xt^T, col-scaled by r
    k_mma_gemm<true, false><<<dim3(SS / 128, QKV / 128, BB), 256, SMEM_GEMM>>>(
        wq_p, xt_p, qkv_p, r_p, nullptr,
        QKV, SS, CC, (size_t)SS * CC, (size_t)QKV * SS);
    // K2: k softmax stats
    k_kstats<<<BB * 512, 256>>>();
    // K3: partial contexts + reduce
    k_context_part<<<dim3(HH, NSPLIT, BB), 256>>>();
    k_ctx_reduce<<<BB * HH * DD * DD / 256, 256>>>();
    // K4: apply q-softmax, write transposed tf32 mid
    k_applyq<<<dim3(SS / 256, HH, BB), 256>>>();
    // K5: out = wo @ midT^T + bias
    k_mma_gemm<false, true><<<dim3(SS / 128, CC / 128, BB), 256, SMEM_GEMM>>>(
        wo_p, midT_p, out, nullptr, b_out,
        CC, SS, CC, (size_t)SS * CC, (size_t)CC * SS);
    // K6: final rms-norm in place
    k_rnorm_out<<<BB * SS / 256, 256>>>(out, gamma2);
}

// round 4
// speedup vs baseline: 5.4484x; 1.4412x over previous
#include <cuda_runtime.h>
#include <cuda_fp16.h>
#include <math.h>
#include <cstdint>

#define BB 16
#define CC 512
#define SS 4096
#define HH 8
#define DD 64
#define QKV 1536
#define NSPLIT 8
#define NSTG 3

// ---------------- scratch (static __device__, allocation-free) ----------------
__device__ __half g_wqh[QKV * CC];                    // (w_qkv*gamma1) fp16
__device__ __half g_woh[CC * CC];                     // w_out fp16
__device__ __half g_xh[(size_t)BB * SS * CC];         // 67 MB  (x^T · r) fp16 [b][s][c]
__device__ float  g_qkv[(size_t)BB * QKV * SS];       // 403 MB
__device__ float  g_kmax[BB * 512];
__device__ float  g_ksum[BB * 512];
__device__ float  g_ctxp[NSPLIT][BB * HH * DD * DD];
__device__ float  g_ctx[BB * HH * DD * DD];
__device__ __half g_mh[(size_t)BB * SS * CC];         // 67 MB  midT fp16 [b][n][c]

// ---------------- helpers ----------------
__device__ __forceinline__ uint32_t smem_u32(const void* p) {
    uint32_t a;
    asm("{ .reg .u64 t; cvta.to.shared.u64 t, %1; cvt.u32.u64 %0, t; }" : "=r"(a) : "l"(p));
    return a;
}
#define CP_ASYNC(dst, src) \
    asm volatile("cp.async.cg.shared.global [%0], [%1], 16;" :: "r"(dst), "l"(src) : "memory")
#define CP_COMMIT() asm volatile("cp.async.commit_group;" ::: "memory")
#define CP_WAIT(n)  asm volatile("cp.async.wait_group %0;" :: "n"(n) : "memory")
#define LDSM4(R, addr) \
    asm volatile("ldmatrix.sync.aligned.m8n8.x4.shared.b16 {%0,%1,%2,%3}, [%4];" \
        : "=r"((R)[0]), "=r"((R)[1]), "=r"((R)[2]), "=r"((R)[3]) : "r"(addr))

__device__ __forceinline__ void mma16(float* c, const uint32_t* a, const uint32_t* b) {
    asm volatile(
        "mma.sync.aligned.m16n8k16.row.col.f32.f16.f16.f32 "
        "{%0,%1,%2,%3},{%4,%5,%6,%7},{%8,%9},{%0,%1,%2,%3};"
        : "+f"(c[0]), "+f"(c[1]), "+f"(c[2]), "+f"(c[3])
        : "r"(a[0]), "r"(a[1]), "r"(a[2]), "r"(a[3]), "r"(b[0]), "r"(b[1]));
}

// ---------------------------------------------------------------------------
// prep: weights -> fp16 scratch (gamma1 folded into w_qkv)
// ---------------------------------------------------------------------------
__global__ void k_prep_wq(const float* __restrict__ w, const float* __restrict__ g1) {
    int i = blockIdx.x * 256 + threadIdx.x;
    g_wqh[i] = __float2half_rn(w[i] * g1[i & (CC - 1)]);
}
__global__ void k_prep_wo(const float* __restrict__ w) {
    int i = blockIdx.x * 256 + threadIdx.x;
    g_woh[i] = __float2half_rn(w[i]);
}

// ---------------------------------------------------------------------------
// normT: fused rms-scale + transpose + fp16:  xh[b][s][c] = fp16(x[b][c][s]*r[b,s])
// grid (SS/32, BB), 256 threads, dyn smem 512x33 tile + 32 scales
// ---------------------------------------------------------------------------
__global__ void k_normT(const float* __restrict__ x) {
    extern __shared__ float sm[];
    float* tile = sm;                  // [512][33]
    float* rr = sm + 512 * 33;         // [32]
    int b = blockIdx.y, s0 = blockIdx.x * 32;
    int t = threadIdx.x;
    const float* xp = x + (size_t)b * CC * SS + s0;

    for (int i = t; i < 512 * 32; i += 256) {
        int c = i >> 5, sl = i & 31;
        tile[c * 33 + sl] = xp[(size_t)c * SS + sl];
    }
    __syncthreads();

    int sl = t >> 3, part = t & 7;
    float acc = 0.f;
    for (int c = part; c < 512; c += 8) {
        float v = tile[c * 33 + sl];
        acc += v * v;
    }
#pragma unroll
    for (int o = 4; o; o >>= 1) acc += __shfl_down_sync(0xFFFFFFFFu, acc, o);
    if (part == 0) rr[sl] = 22.62741699796952f / fmaxf(sqrtf(acc), 1e-12f);
    __syncthreads();

    float rv = rr[sl];
    __half* op = g_xh + ((size_t)b * SS + s0 + sl) * CC;
    for (int c0 = part * 64; c0 < part * 64 + 64; c0 += 8) {
        __half h[8];
#pragma unroll
        for (int j = 0; j < 8; j++) h[j] = __float2half_rn(tile[(c0 + j) * 33 + sl] * rv);
        *(uint4*)(op + c0) = *(uint4*)h;
    }
}

// ---------------------------------------------------------------------------
// fp16 mma.sync GEMM: C[b][M,N] = A[M,K] @ B[b][N,K]^T   (A,B fp16, C fp32)
// CTA 128x128, BK=64, 3-stage cp.async, ldmatrix.x4 fragments, 8 warps 64x32.
// SMEM row = 64 halves = 128B, swizzle: chunk ^= row&7.
// ---------------------------------------------------------------------------
template <bool BI>
__global__ __launch_bounds__(256, 2)
void k_hgemm(const __half* __restrict__ A, const __half* __restrict__ Bg,
             float* __restrict__ Cg, const float* __restrict__ bias,
             int M, int Ntot, int K, size_t strB, size_t strC) {
    extern __shared__ char smc[];
    uint32_t sbase = smem_u32(smc);

    int tid = threadIdx.x, lane = tid & 31, wid = tid >> 5;
    int b = blockIdx.z, m0 = blockIdx.y * 128, n0 = blockIdx.x * 128;
    const __half* Ab = A + (size_t)m0 * K;
    const __half* Bb = Bg + (size_t)b * strB + (size_t)n0 * K;

    const int NC = K / 64;

    auto issue = [&](int kc, int buf) {
        const __half* Asrc = Ab + kc * 64;
        const __half* Bsrc = Bb + kc * 64;
        uint32_t base = sbase + buf * 32768;
#pragma unroll
        for (int it = 0; it < 4; it++) {
            int id = it * 256 + tid;                  // 0..1023 16B chunks
            int row = id >> 3, j = id & 7;
            uint32_t dst = base + row * 128 + ((j ^ (row & 7)) << 4);
            CP_ASYNC(dst, Asrc + (size_t)row * K + j * 8);
            CP_ASYNC(dst + 16384, Bsrc + (size_t)row * K + j * 8);
        }
    };

#pragma unroll
    for (int s = 0; s < NSTG; s++) { issue(s, s); CP_COMMIT(); }

    int wm = (wid >> 2) * 64, wn = (wid & 3) * 32;
    int rA = wm + (lane & 7) + ((lane >> 3) & 1) * 8;   // A ldsm row (mi*16 added)
    int cA = (lane >> 4);                               // A extra k-chunk bit
    int rB = wn + (lane & 7) + ((lane >> 4) & 1) * 8;   // B ldsm row (pair*16 added)
    int cB = (lane >> 3) & 1;
    int swA = rA & 7, swB = rB & 7;

    float acc[4][4][4] = {};

    for (int kc = 0; kc < NC; kc++) {
        CP_WAIT(NSTG - 1);
        __syncthreads();
        uint32_t bufA = sbase + (kc % NSTG) * 32768;
        uint32_t bufB = bufA + 16384;
#pragma unroll
        for (int ks = 0; ks < 4; ks++) {
            uint32_t a[4][4], bf[2][4];
            uint32_t kchA = ((uint32_t)(ks * 2 + cA) ^ swA) << 4;
            uint32_t kchB = ((uint32_t)(ks * 2 + cB) ^ swB) << 4;
#pragma unroll
            for (int mi = 0; mi < 4; mi++)
                LDSM4(a[mi], bufA + (rA + mi * 16) * 128 + kchA);
#pragma unroll
            for (int p = 0; p < 2; p++)
                LDSM4(bf[p], bufB + (rB + p * 16) * 128 + kchB);
#pragma unroll
            for (int mi = 0; mi < 4; mi++)
#pragma unroll
                for (int ni = 0; ni < 4; ni++)
                    mma16(acc[mi][ni], a[mi], bf[ni >> 1] + (ni & 1) * 2);
        }
        __syncthreads();
        if (kc + NSTG < NC) issue(kc + NSTG, kc % NSTG);
        CP_COMMIT();
    }

    float* Cd = Cg + (size_t)b * strC;
#pragma unroll
    for (int mi = 0; mi < 4; mi++) {
        int r0 = m0 + wm + mi * 16 + (lane >> 2);
        float bi0 = BI ? bias[r0] : 0.f;
        float bi1 = BI ? bias[r0 + 8] : 0.f;
#pragma unroll
        for (int ni = 0; ni < 4; ni++) {
            int c = n0 + wn + (ni >> 1) * 16 + (ni & 1) * 8 + (lane & 3) * 2;
            *(float2*)(Cd + (size_t)r0 * Ntot + c) =
                make_float2(acc[mi][ni][0] + bi0, acc[mi][ni][1] + bi0);
            *(float2*)(Cd + (size_t)(r0 + 8) * Ntot + c) =
                make_float2(acc[mi][ni][2] + bi1, acc[mi][ni][3] + bi1);
        }
    }
}

// ---------------------------------------------------------------------------
// K2: per-row (over n) max & sumexp for k
// ---------------------------------------------------------------------------
__global__ void k_kstats() {
    int row = blockIdx.x;
    int b = row >> 9, o = row & 511;
    const float* p = g_qkv + ((size_t)b * QKV + 512 + o) * SS;
    __shared__ float red[256];
    int t = threadIdx.x;
    float mx = -3.402823466e38f;
    for (int i = t; i < SS; i += 256) mx = fmaxf(mx, p[i]);
    red[t] = mx; __syncthreads();
    for (int st = 128; st > 0; st >>= 1) {
        if (t < st) red[t] = fmaxf(red[t], red[t + st]);
        __syncthreads();
    }
    mx = red[0]; __syncthreads();
    float sm = 0.f;
    for (int i = t; i < SS; i += 256) sm += expf(p[i] - mx);
    red[t] = sm; __syncthreads();
    for (int st = 128; st > 0; st >>= 1) {
        if (t < st) red[t] += red[t + st];
        __syncthreads();
    }
    if (t == 0) { g_kmax[row] = mx; g_ksum[row] = red[0]; }
}

// ---------------------------------------------------------------------------
// K3: partial ctx over n-segment; grid (HH, NSPLIT, BB)
// ---------------------------------------------------------------------------
__global__ __launch_bounds__(256, 1)
void k_context_part() {
    int h = blockIdx.x, seg = blockIdx.y, b = blockIdx.z;
    const float* kp = g_qkv + ((size_t)b * QKV + 512 + h * 64) * SS;
    const float* vp = g_qkv + ((size_t)b * QKV + 1024 + h * 64) * SS;

    __shared__ float ks[64][68];
    __shared__ float vs[64][68];
    __shared__ float mx_s[64], is_s[64];

    int tid = threadIdx.x;
    if (tid < 64) {
        int base = b * 512 + h * 64 + tid;
        mx_s[tid] = g_kmax[base];
        is_s[tid] = 1.f / g_ksum[base];
    }
    __syncthreads();

    int td = (tid >> 4) * 4, te = (tid & 15) * 4;
    float acc[4][4] = {};

    int nbeg = seg * (SS / NSPLIT), nend = nbeg + SS / NSPLIT;
    for (int n0 = nbeg; n0 < nend; n0 += 64) {
        __syncthreads();
#pragma unroll
        for (int it = 0; it < 4; it++) {
            int f = it * 256 + tid;
            int dr = f >> 4, nl = (f & 15) * 4;
            float m = mx_s[dr], s = is_s[dr];
            float4 kv = *(const float4*)(kp + (size_t)dr * SS + n0 + nl);
            ks[nl + 0][dr] = expf(kv.x - m) * s;
            ks[nl + 1][dr] = expf(kv.y - m) * s;
            ks[nl + 2][dr] = expf(kv.z - m) * s;
            ks[nl + 3][dr] = expf(kv.w - m) * s;
            float4 vv = *(const float4*)(vp + (size_t)dr * SS + n0 + nl);
            vs[nl + 0][dr] = vv.x; vs[nl + 1][dr] = vv.y;
            vs[nl + 2][dr] = vv.z; vs[nl + 3][dr] = vv.w;
        }
        __syncthreads();
#pragma unroll 4
        for (int nn = 0; nn < 64; nn++) {
            float a[4], bv[4];
            *(float4*)a  = *(const float4*)&ks[nn][td];
            *(float4*)bv = *(const float4*)&vs[nn][te];
#pragma unroll
            for (int i = 0; i < 4; i++)
#pragma unroll
                for (int j = 0; j < 4; j++) acc[i][j] += a[i] * bv[j];
        }
    }
    float* cp = g_ctxp[seg] + (size_t)(b * HH + h) * DD * DD;
#pragma unroll
    for (int i = 0; i < 4; i++)
        *(float4*)&cp[(td + i) * 64 + te] = *(float4*)acc[i];
}

__global__ void k_ctx_reduce() {
    int i = blockIdx.x * 256 + threadIdx.x;
    float s = 0.f;
#pragma unroll
    for (int p = 0; p < NSPLIT; p++) s += g_ctxp[p][i];
    g_ctx[i] = s;
}

// ---------------------------------------------------------------------------
// K4: mh[b, n, h*64+e] = fp16( sum_d ctx[d,e] * softmax_d(q)[d,n] * D^-0.5 )
// ---------------------------------------------------------------------------
__global__ __launch_bounds__(256, 1)
void k_applyq() {
    int b = blockIdx.z, h = blockIdx.y;
    int n = blockIdx.x * 256 + threadIdx.x;

    __shared__ float cs[64][64];
    const float* ctxp = g_ctx + (size_t)(b * HH + h) * DD * DD;
    for (int i = threadIdx.x; i < 4096; i += 256) ((float*)cs)[i] = ctxp[i];
    __syncthreads();

    const float* qp = g_qkv + ((size_t)b * QKV + h * 64) * SS + n;
    float p[64];
    float mx = -3.402823466e38f;
#pragma unroll
    for (int d = 0; d < 64; d++) { p[d] = qp[(size_t)d * SS]; mx = fmaxf(mx, p[d]); }
    float sm = 0.f;
#pragma unroll
    for (int d = 0; d < 64; d++) { p[d] = expf(p[d] - mx); sm += p[d]; }
    float sc = 0.125f / sm;

    float acc[64] = {};
#pragma unroll 4
    for (int d = 0; d < 64; d++) {
        float pv = p[d] * sc;
#pragma unroll
        for (int e = 0; e < 64; e += 4) {
            float4 c4 = *(const float4*)&cs[d][e];
            acc[e + 0] += c4.x * pv; acc[e + 1] += c4.y * pv;
            acc[e + 2] += c4.z * pv; acc[e + 3] += c4.w * pv;
        }
    }
    __half* op = g_mh + ((size_t)b * SS + n) * CC + h * 64;
#pragma unroll
    for (int e = 0; e < 64; e += 8) {
        __half hh[8];
#pragma unroll
        for (int j = 0; j < 8; j++) hh[j] = __float2half_rn(acc[e + j]);
        *(uint4*)(op + e) = *(uint4*)hh;
    }
}

// ---------------------------------------------------------------------------
// K6: in-place final rms-norm on d_out
// ---------------------------------------------------------------------------
__global__ void k_rnorm_out(float* __restrict__ y, const float* __restrict__ gamma2) {
    int idx = blockIdx.x * 256 + threadIdx.x;
    int b = idx >> 12, s = idx & (SS - 1);
    float* p = y + (size_t)b * CC * SS + s;
    float acc = 0.f;
#pragma unroll 8
    for (int c = 0; c < CC; c++) { float v = p[(size_t)c * SS]; acc += v * v; }
    float sc = 22.62741699796952f / fmaxf(sqrtf(acc), 1e-12f);
#pragma unroll 8
    for (int c = 0; c < CC; c++) p[(size_t)c * SS] *= sc * gamma2[c];
}

// ---------------------------------------------------------------------------
extern "C" void kernel_launch(void* const* d_in, const int* in_sizes, int n_in,
                              void* d_out, int out_size) {
    const float* x      = (const float*)d_in[0];
    const float* gamma1 = (const float*)d_in[1];
    const float* w_qkv  = (const float*)d_in[2];
    const float* w_out  = (const float*)d_in[3];
    const float* b_out  = (const float*)d_in[4];
    const float* gamma2 = (const float*)d_in[5];
    float* out = (float*)d_out;

    __half *wqh_p, *woh_p, *xh_p, *mh_p;
    float *qkv_p;
    cudaGetSymbolAddress((void**)&wqh_p, g_wqh);
    cudaGetSymbolAddress((void**)&woh_p, g_woh);
    cudaGetSymbolAddress((void**)&xh_p,  g_xh);
    cudaGetSymbolAddress((void**)&mh_p,  g_mh);
    cudaGetSymbolAddress((void**)&qkv_p, g_qkv);

    const int SMEM_NT = (512 * 33 + 32) * 4;           // 67712
    const int SMEM_GEMM = NSTG * 32768;                // 98304
    cudaFuncSetAttribute(k_normT, cudaFuncAttributeMaxDynamicSharedMemorySize, SMEM_NT);
    cudaFuncSetAttribute(k_hgemm<false>, cudaFuncAttributeMaxDynamicSharedMemorySize, SMEM_GEMM);
    cudaFuncSetAttribute(k_hgemm<true>,  cudaFuncAttributeMaxDynamicSharedMemorySize, SMEM_GEMM);

    // prep weights (fp16, gamma folded)
    k_prep_wq<<<QKV * CC / 256, 256>>>(w_qkv, gamma1);
    k_prep_wo<<<CC * CC / 256, 256>>>(w_out);
    // fused rms-scale + transpose + fp16
    k_normT<<<dim3(SS / 32, BB), 256, SMEM_NT>>>(x);
    // K1: qkv = wqh @ xh^T  (fp16 tensor cores, fp32 out)
    k_hgemm<false><<<dim3(SS / 128, QKV / 128, BB), 256, SMEM_GEMM>>>(
        wqh_p, xh_p, qkv_p, nullptr,
        QKV, SS, CC, (size_t)SS * CC, (size_t)QKV * SS);
    // K2: k softmax stats
    k_kstats<<<BB * 512, 256>>>();
    // K3: partial contexts + reduce
    k_context_part<<<dim3(HH, NSPLIT, BB), 256>>>();
    k_ctx_reduce<<<BB * HH * DD * DD / 256, 256>>>();
    // K4: apply q-softmax, write fp16 midT
    k_applyq<<<dim3(SS / 256, HH, BB), 256>>>();
    // K5: out = woh @ mh^T + bias
    k_hgemm<true><<<dim3(SS / 128, CC / 128, BB), 256, SMEM_GEMM>>>(
        woh_p, mh_p, out, b_out,
        CC, SS, CC, (size_t)SS * CC, (size_t)CC * SS);
    // K6: final rms-norm in place
    k_rnorm_out<<<BB * SS / 256, 256>>>(out, gamma2);
}

// round 5
// speedup vs baseline: 5.9001x; 1.0829x over previous
#include <cuda_runtime.h>
#include <cuda_fp16.h>
#include <math.h>
#include <cstdint>

#define BB 16
#define CC 512
#define SS 4096
#define HH 8
#define DD 64
#define QKV 1536
#define NSPLIT 16
#define NSTG 3

// ---------------- scratch (static __device__, allocation-free) ----------------
__device__ __half g_wqh[QKV * CC];                    // (w_qkv*gamma1) fp16
__device__ __half g_woh[CC * CC];                     // w_out fp16
__device__ __half g_xh[(size_t)BB * SS * CC];         // 67 MB  (x^T · r) fp16 [b][s][c]
__device__ __half g_qkvh[(size_t)BB * QKV * SS];      // 201 MB qkv fp16 [b][1536][s]
__device__ float  g_kmax[BB * 512];
__device__ float  g_ksum[BB * 512];
__device__ float  g_ctxp[NSPLIT][BB * HH * DD * DD];
__device__ float  g_ctx[BB * HH * DD * DD];
__device__ __half g_mh[(size_t)BB * SS * CC];         // 67 MB  midT fp16 [b][n][c]

// ---------------- helpers ----------------
__device__ __forceinline__ uint32_t smem_u32(const void* p) {
    uint32_t a;
    asm("{ .reg .u64 t; cvta.to.shared.u64 t, %1; cvt.u32.u64 %0, t; }" : "=r"(a) : "l"(p));
    return a;
}
#define CP_ASYNC(dst, src) \
    asm volatile("cp.async.cg.shared.global [%0], [%1], 16;" :: "r"(dst), "l"(src) : "memory")
#define CP_COMMIT() asm volatile("cp.async.commit_group;" ::: "memory")
#define CP_WAIT(n)  asm volatile("cp.async.wait_group %0;" :: "n"(n) : "memory")
#define LDSM4(R, addr) \
    asm volatile("ldmatrix.sync.aligned.m8n8.x4.shared.b16 {%0,%1,%2,%3}, [%4];" \
        : "=r"((R)[0]), "=r"((R)[1]), "=r"((R)[2]), "=r"((R)[3]) : "r"(addr))

__device__ __forceinline__ void mma16(float* c, const uint32_t* a, const uint32_t* b) {
    asm volatile(
        "mma.sync.aligned.m16n8k16.row.col.f32.f16.f16.f32 "
        "{%0,%1,%2,%3},{%4,%5,%6,%7},{%8,%9},{%0,%1,%2,%3};"
        : "+f"(c[0]), "+f"(c[1]), "+f"(c[2]), "+f"(c[3])
        : "r"(a[0]), "r"(a[1]), "r"(a[2]), "r"(a[3]), "r"(b[0]), "r"(b[1]));
}

// ---------------------------------------------------------------------------
// prep: weights -> fp16 scratch (gamma1 folded into w_qkv)
// ---------------------------------------------------------------------------
__global__ void k_prep_wq(const float* __restrict__ w, const float* __restrict__ g1) {
    int i = blockIdx.x * 256 + threadIdx.x;
    g_wqh[i] = __float2half_rn(w[i] * g1[i & (CC - 1)]);
}
__global__ void k_prep_wo(const float* __restrict__ w) {
    int i = blockIdx.x * 256 + threadIdx.x;
    g_woh[i] = __float2half_rn(w[i]);
}

// ---------------------------------------------------------------------------
// normT: xh[b][s][c] = fp16(x[b][c][s]*r[b,s])
// ---------------------------------------------------------------------------
__global__ void k_normT(const float* __restrict__ x) {
    extern __shared__ float sm[];
    float* tile = sm;                  // [512][33]
    float* rr = sm + 512 * 33;         // [32]
    int b = blockIdx.y, s0 = blockIdx.x * 32;
    int t = threadIdx.x;
    const float* xp = x + (size_t)b * CC * SS + s0;

    for (int i = t; i < 512 * 32; i += 256) {
        int c = i >> 5, sl = i & 31;
        tile[c * 33 + sl] = xp[(size_t)c * SS + sl];
    }
    __syncthreads();

    int sl = t >> 3, part = t & 7;
    float acc = 0.f;
    for (int c = part; c < 512; c += 8) {
        float v = tile[c * 33 + sl];
        acc += v * v;
    }
#pragma unroll
    for (int o = 4; o; o >>= 1) acc += __shfl_down_sync(0xFFFFFFFFu, acc, o);
    if (part == 0) rr[sl] = 22.62741699796952f / fmaxf(sqrtf(acc), 1e-12f);
    __syncthreads();

    float rv = rr[sl];
    __half* op = g_xh + ((size_t)b * SS + s0 + sl) * CC;
    for (int c0 = part * 64; c0 < part * 64 + 64; c0 += 8) {
        __half h[8];
#pragma unroll
        for (int j = 0; j < 8; j++) h[j] = __float2half_rn(tile[(c0 + j) * 33 + sl] * rv);
        *(uint4*)(op + c0) = *(uint4*)h;
    }
}

// ---------------------------------------------------------------------------
// K1: fp16 GEMM -> fp16 out.  qkv[b][M,N] = wq[M,K] @ xh[b][N,K]^T
// CTA 128x128, BK=64, 3-stage, 8 warps 64x32, 2 CTAs/SM.
// ---------------------------------------------------------------------------
__global__ __launch_bounds__(256, 2)
void k_hgemm(const __half* __restrict__ A, const __half* __restrict__ Bg,
             __half* __restrict__ Cg, int M, int Ntot, int K,
             size_t strB, size_t strC) {
    extern __shared__ char smc[];
    uint32_t sbase = smem_u32(smc);

    int tid = threadIdx.x, lane = tid & 31, wid = tid >> 5;
    int b = blockIdx.z, m0 = blockIdx.y * 128, n0 = blockIdx.x * 128;
    const __half* Ab = A + (size_t)m0 * K;
    const __half* Bb = Bg + (size_t)b * strB + (size_t)n0 * K;

    const int NC = K / 64;

    auto issue = [&](int kc, int buf) {
        const __half* Asrc = Ab + kc * 64;
        const __half* Bsrc = Bb + kc * 64;
        uint32_t base = sbase + buf * 32768;
#pragma unroll
        for (int it = 0; it < 4; it++) {
            int id = it * 256 + tid;
            int row = id >> 3, j = id & 7;
            uint32_t dst = base + row * 128 + ((j ^ (row & 7)) << 4);
            CP_ASYNC(dst, Asrc + (size_t)row * K + j * 8);
            CP_ASYNC(dst + 16384, Bsrc + (size_t)row * K + j * 8);
        }
    };

#pragma unroll
    for (int s = 0; s < NSTG; s++) { issue(s, s); CP_COMMIT(); }

    int wm = (wid >> 2) * 64, wn = (wid & 3) * 32;
    int rA = wm + (lane & 7) + ((lane >> 3) & 1) * 8;
    int cA = (lane >> 4);
    int rB = wn + (lane & 7) + ((lane >> 4) & 1) * 8;
    int cB = (lane >> 3) & 1;
    int swA = rA & 7, swB = rB & 7;

    float acc[4][4][4] = {};

    for (int kc = 0; kc < NC; kc++) {
        CP_WAIT(NSTG - 1);
        __syncthreads();
        uint32_t bufA = sbase + (kc % NSTG) * 32768;
        uint32_t bufB = bufA + 16384;
#pragma unroll
        for (int ks = 0; ks < 4; ks++) {
            uint32_t a[4][4], bf[2][4];
            uint32_t kchA = ((uint32_t)(ks * 2 + cA) ^ swA) << 4;
            uint32_t kchB = ((uint32_t)(ks * 2 + cB) ^ swB) << 4;
#pragma unroll
            for (int mi = 0; mi < 4; mi++)
                LDSM4(a[mi], bufA + (rA + mi * 16) * 128 + kchA);
#pragma unroll
            for (int p = 0; p < 2; p++)
                LDSM4(bf[p], bufB + (rB + p * 16) * 128 + kchB);
#pragma unroll
            for (int mi = 0; mi < 4; mi++)
#pragma unroll
                for (int ni = 0; ni < 4; ni++)
                    mma16(acc[mi][ni], a[mi], bf[ni >> 1] + (ni & 1) * 2);
        }
        __syncthreads();
        if (kc + NSTG < NC) issue(kc + NSTG, kc % NSTG);
        CP_COMMIT();
    }

    __half* Cd = Cg + (size_t)b * strC;
#pragma unroll
    for (int mi = 0; mi < 4; mi++) {
        int r0 = m0 + wm + mi * 16 + (lane >> 2);
#pragma unroll
        for (int ni = 0; ni < 4; ni++) {
            int c = n0 + wn + (ni >> 1) * 16 + (ni & 1) * 8 + (lane & 3) * 2;
            *(__half2*)(Cd + (size_t)r0 * Ntot + c) =
                __floats2half2_rn(acc[mi][ni][0], acc[mi][ni][1]);
            *(__half2*)(Cd + (size_t)(r0 + 8) * Ntot + c) =
                __floats2half2_rn(acc[mi][ni][2], acc[mi][ni][3]);
        }
    }
}

// ---------------------------------------------------------------------------
// K2: per-row (over n) max & sumexp for k (fp16 source)
// ---------------------------------------------------------------------------
__global__ void k_kstats() {
    int row = blockIdx.x;
    int b = row >> 9, o = row & 511;
    const __half* p = g_qkvh + ((size_t)b * QKV + 512 + o) * SS;
    __shared__ float red[256];
    int t = threadIdx.x;
    float mx = -3.402823466e38f;
    for (int i = t; i < SS; i += 256) mx = fmaxf(mx, __half2float(p[i]));
    red[t] = mx; __syncthreads();
    for (int st = 128; st > 0; st >>= 1) {
        if (t < st) red[t] = fmaxf(red[t], red[t + st]);
        __syncthreads();
    }
    mx = red[0]; __syncthreads();
    float sm = 0.f;
    for (int i = t; i < SS; i += 256) sm += expf(__half2float(p[i]) - mx);
    red[t] = sm; __syncthreads();
    for (int st = 128; st > 0; st >>= 1) {
        if (t < st) red[t] += red[t + st];
        __syncthreads();
    }
    if (t == 0) { g_kmax[row] = mx; g_ksum[row] = red[0]; }
}

// ---------------------------------------------------------------------------
// K3: partial ctx over n-segment; grid (HH, NSPLIT, BB), fp16 k/v
// ---------------------------------------------------------------------------
__global__ __launch_bounds__(256, 1)
void k_context_part() {
    int h = blockIdx.x, seg = blockIdx.y, b = blockIdx.z;
    const __half* kp = g_qkvh + ((size_t)b * QKV + 512 + h * 64) * SS;
    const __half* vp = g_qkvh + ((size_t)b * QKV + 1024 + h * 64) * SS;

    __shared__ float ks[64][68];
    __shared__ float vs[64][68];
    __shared__ float mx_s[64], is_s[64];

    int tid = threadIdx.x;
    if (tid < 64) {
        int base = b * 512 + h * 64 + tid;
        mx_s[tid] = g_kmax[base];
        is_s[tid] = 1.f / g_ksum[base];
    }
    __syncthreads();

    int td = (tid >> 4) * 4, te = (tid & 15) * 4;
    float acc[4][4] = {};

    int nbeg = seg * (SS / NSPLIT), nend = nbeg + SS / NSPLIT;
    for (int n0 = nbeg; n0 < nend; n0 += 64) {
        __syncthreads();
#pragma unroll
        for (int it = 0; it < 2; it++) {
            int f = it * 256 + tid;                 // 0..511 chunks of 8 halves
            int dr = f >> 3, nl = (f & 7) * 8;
            float m = mx_s[dr], s = is_s[dr];
            uint4 kraw = *(const uint4*)(kp + (size_t)dr * SS + n0 + nl);
            uint4 vraw = *(const uint4*)(vp + (size_t)dr * SS + n0 + nl);
            const __half* kh = (const __half*)&kraw;
            const __half* vh = (const __half*)&vraw;
#pragma unroll
            for (int j = 0; j < 8; j++) {
                ks[nl + j][dr] = expf(__half2float(kh[j]) - m) * s;
                vs[nl + j][dr] = __half2float(vh[j]);
            }
        }
        __syncthreads();
#pragma unroll 4
        for (int nn = 0; nn < 64; nn++) {
            float a[4], bv[4];
            *(float4*)a  = *(const float4*)&ks[nn][td];
            *(float4*)bv = *(const float4*)&vs[nn][te];
#pragma unroll
            for (int i = 0; i < 4; i++)
#pragma unroll
                for (int j = 0; j < 4; j++) acc[i][j] += a[i] * bv[j];
        }
    }
    float* cp = g_ctxp[seg] + (size_t)(b * HH + h) * DD * DD;
#pragma unroll
    for (int i = 0; i < 4; i++)
        *(float4*)&cp[(td + i) * 64 + te] = *(float4*)acc[i];
}

__global__ void k_ctx_reduce() {
    int i = blockIdx.x * 256 + threadIdx.x;
    float s = 0.f;
#pragma unroll
    for (int p = 0; p < NSPLIT; p++) s += g_ctxp[p][i];
    g_ctx[i] = s;
}

// ---------------------------------------------------------------------------
// K4: mh[b, n, h*64+e] = fp16( sum_d ctx[d,e] * softmax_d(q)[d,n] * D^-0.5 )
// ---------------------------------------------------------------------------
__global__ __launch_bounds__(256, 1)
void k_applyq() {
    int b = blockIdx.z, h = blockIdx.y;
    int n = blockIdx.x * 256 + threadIdx.x;

    __shared__ float cs[64][64];
    const float* ctxp = g_ctx + (size_t)(b * HH + h) * DD * DD;
    for (int i = threadIdx.x; i < 4096; i += 256) ((float*)cs)[i] = ctxp[i];
    __syncthreads();

    const __half* qp = g_qkvh + ((size_t)b * QKV + h * 64) * SS + n;
    float p[64];
    float mx = -3.402823466e38f;
#pragma unroll
    for (int d = 0; d < 64; d++) {
        p[d] = __half2float(qp[(size_t)d * SS]);
        mx = fmaxf(mx, p[d]);
    }
    float sm = 0.f;
#pragma unroll
    for (int d = 0; d < 64; d++) { p[d] = expf(p[d] - mx); sm += p[d]; }
    float sc = 0.125f / sm;

    float acc[64] = {};
#pragma unroll 4
    for (int d = 0; d < 64; d++) {
        float pv = p[d] * sc;
#pragma unroll
        for (int e = 0; e < 64; e += 4) {
            float4 c4 = *(const float4*)&cs[d][e];
            acc[e + 0] += c4.x * pv; acc[e + 1] += c4.y * pv;
            acc[e + 2] += c4.z * pv; acc[e + 3] += c4.w * pv;
        }
    }
    __half* op = g_mh + ((size_t)b * SS + n) * CC + h * 64;
#pragma unroll
    for (int e = 0; e < 64; e += 8) {
        __half hh[8];
#pragma unroll
        for (int j = 0; j < 8; j++) hh[j] = __float2half_rn(acc[e + j]);
        *(uint4*)(op + e) = *(uint4*)hh;
    }
}

// ---------------------------------------------------------------------------
// K5: out[b][512][n-tile] = rmsnorm( wo @ mh^T + bias ) * gamma2
// Tall tile: full M=512 per CTA, N-tile 64, BK=32, 512 threads (16 warps 64x32).
// Per-column sumsq reduced in-warp (butterfly) + smem atomics -> scale -> store.
// ---------------------------------------------------------------------------
__global__ __launch_bounds__(512, 1)
void k_ogemm(const __half* __restrict__ A, const __half* __restrict__ Bg,
             float* __restrict__ out, const float* __restrict__ bias,
             const float* __restrict__ gamma2) {
    extern __shared__ char smc[];
    const int STG = 36864;                             // A 32KB + B 4KB
    uint32_t sbase = smem_u32(smc);
    float* colsq = (float*)(smc + 3 * STG);            // [64]
    float* csc   = colsq + 64;                         // [64]

    int tid = threadIdx.x, lane = tid & 31, wid = tid >> 5;
    int b = blockIdx.y, n0 = blockIdx.x * 64;
    const __half* Bb = Bg + ((size_t)b * SS + n0) * CC;

    if (tid < 64) colsq[tid] = 0.f;

    auto issue = [&](int kc, int buf) {
        uint32_t base = sbase + buf * STG;
#pragma unroll
        for (int it = 0; it < 4; it++) {
            int id = it * 512 + tid;                   // A: 2048 chunks
            int row = id >> 2, j = id & 3;
            uint32_t dst = base + row * 64 + (((uint32_t)j ^ ((row >> 1) & 3)) << 4);
            CP_ASYNC(dst, A + (size_t)row * CC + kc * 32 + j * 8);
        }
        if (tid < 256) {                               // B: 256 chunks
            int row = tid >> 2, j = tid & 3;
            uint32_t dst = base + 32768 + row * 64 + (((uint32_t)j ^ ((row >> 1) & 3)) << 4);
            CP_ASYNC(dst, Bb + (size_t)row * CC + kc * 32 + j * 8);
        }
    };

#pragma unroll
    for (int s = 0; s < NSTG; s++) { issue(s, s); CP_COMMIT(); }

    int wm = (wid >> 1) * 64, wn = (wid & 1) * 32;
    int rA = wm + (lane & 7) + ((lane >> 3) & 1) * 8;
    int cA = (lane >> 4);
    int rB = wn + (lane & 7) + ((lane >> 4) & 1) * 8;
    int cB = (lane >> 3) & 1;
    int swA = (rA >> 1) & 3, swB = (rB >> 1) & 3;

    float acc[4][4][4] = {};
    const int NC = CC / 32;                            // 16

    for (int kc = 0; kc < NC; kc++) {
        CP_WAIT(NSTG - 1);
        __syncthreads();
        uint32_t bufA = sbase + (kc % NSTG) * STG;
        uint32_t bufB = bufA + 32768;
#pragma unroll
        for (int ks = 0; ks < 2; ks++) {
            uint32_t a[4][4], bf[2][4];
            uint32_t kchA = ((uint32_t)(ks * 2 + cA) ^ swA) << 4;
            uint32_t kchB = ((uint32_t)(ks * 2 + cB) ^ swB) << 4;
#pragma unroll
            for (int mi = 0; mi < 4; mi++)
                LDSM4(a[mi], bufA + (rA + mi * 16) * 64 + kchA);
#pragma unroll
            for (int p = 0; p < 2; p++)
                LDSM4(bf[p], bufB + (rB + p * 16) * 64 + kchB);
#pragma unroll
            for (int mi = 0; mi < 4; mi++)
#pragma unroll
                for (int ni = 0; ni < 4; ni++)
                    mma16(acc[mi][ni], a[mi], bf[ni >> 1] + (ni & 1) * 2);
        }
        __syncthreads();
        if (kc + NSTG < NC) issue(kc + NSTG, kc % NSTG);
        CP_COMMIT();
    }

    // bias + per-column sum of squares
    float bi0[4], bi1[4];
#pragma unroll
    for (int mi = 0; mi < 4; mi++) {
        bi0[mi] = bias[wm + mi * 16 + (lane >> 2)];
        bi1[mi] = bias[wm + mi * 16 + (lane >> 2) + 8];
    }
#pragma unroll
    for (int ni = 0; ni < 4; ni++) {
        float l0 = 0.f, l1 = 0.f;
#pragma unroll
        for (int mi = 0; mi < 4; mi++) {
            acc[mi][ni][0] += bi0[mi]; acc[mi][ni][1] += bi0[mi];
            acc[mi][ni][2] += bi1[mi]; acc[mi][ni][3] += bi1[mi];
            l0 += acc[mi][ni][0] * acc[mi][ni][0] + acc[mi][ni][2] * acc[mi][ni][2];
            l1 += acc[mi][ni][1] * acc[mi][ni][1] + acc[mi][ni][3] * acc[mi][ni][3];
        }
#pragma unroll
        for (int o = 4; o <= 16; o <<= 1) {
            l0 += __shfl_xor_sync(0xFFFFFFFFu, l0, o);
            l1 += __shfl_xor_sync(0xFFFFFFFFu, l1, o);
        }
        if ((lane >> 2) == 0) {
            int cloc = wn + (ni >> 1) * 16 + (ni & 1) * 8 + (lane & 3) * 2;
            atomicAdd(colsq + cloc, l0);
            atomicAdd(colsq + cloc + 1, l1);
        }
    }
    __syncthreads();
    if (tid < 64)
        csc[tid] = 22.62741699796952f / fmaxf(sqrtf(colsq[tid]), 1e-12f);
    __syncthreads();

    float* Cd = out + (size_t)b * CC * SS + n0;
#pragma unroll
    for (int mi = 0; mi < 4; mi++) {
        int r0 = wm + mi * 16 + (lane >> 2);
        float g0 = gamma2[r0], g1 = gamma2[r0 + 8];
#pragma unroll
        for (int ni = 0; ni < 4; ni++) {
            int cloc = wn + (ni >> 1) * 16 + (ni & 1) * 8 + (lane & 3) * 2;
            float s0 = csc[cloc], s1 = csc[cloc + 1];
            *(float2*)(Cd + (size_t)r0 * SS + cloc) =
                make_float2(acc[mi][ni][0] * s0 * g0, acc[mi][ni][1] * s1 * g0);
            *(float2*)(Cd + (size_t)(r0 + 8) * SS + cloc) =
                make_float2(acc[mi][ni][2] * s0 * g1, acc[mi][ni][3] * s1 * g1);
        }
    }
}

// ---------------------------------------------------------------------------
extern "C" void kernel_launch(void* const* d_in, const int* in_sizes, int n_in,
                              void* d_out, int out_size) {
    const float* x      = (const float*)d_in[0];
    const float* gamma1 = (const float*)d_in[1];
    const float* w_qkv  = (const float*)d_in[2];
    const float* w_out  = (const float*)d_in[3];
    const float* b_out  = (const float*)d_in[4];
    const float* gamma2 = (const float*)d_in[5];
    float* out = (float*)d_out;

    __half *wqh_p, *woh_p, *xh_p, *mh_p, *qkvh_p;
    cudaGetSymbolAddress((void**)&wqh_p,  g_wqh);
    cudaGetSymbolAddress((void**)&woh_p,  g_woh);
    cudaGetSymbolAddress((void**)&xh_p,   g_xh);
    cudaGetSymbolAddress((void**)&mh_p,   g_mh);
    cudaGetSymbolAddress((void**)&qkvh_p, g_qkvh);

    const int SMEM_NT = (512 * 33 + 32) * 4;
    const int SMEM_G1 = NSTG * 32768;                  // 98304
    const int SMEM_G5 = NSTG * 36864 + 512;            // 111104
    cudaFuncSetAttribute(k_normT, cudaFuncAttributeMaxDynamicSharedMemorySize, SMEM_NT);
    cudaFuncSetAttribute(k_hgemm, cudaFuncAttributeMaxDynamicSharedMemorySize, SMEM_G1);
    cudaFuncSetAttribute(k_ogemm, cudaFuncAttributeMaxDynamicSharedMemorySize, SMEM_G5);

    k_prep_wq<<<QKV * CC / 256, 256>>>(w_qkv, gamma1);
    k_prep_wo<<<CC * CC / 256, 256>>>(w_out);
    k_normT<<<dim3(SS / 32, BB), 256, SMEM_NT>>>(x);
    // K1: qkv (fp16 out)
    k_hgemm<<<dim3(SS / 128, QKV / 128, BB), 256, SMEM_G1>>>(
        wqh_p, xh_p, qkvh_p, QKV, SS, CC, (size_t)SS * CC, (size_t)QKV * SS);
    // K2: k softmax stats
    k_kstats<<<BB * 512, 256>>>();
    // K3: partial contexts + reduce
    k_context_part<<<dim3(HH, NSPLIT, BB), 256>>>();
    k_ctx_reduce<<<BB * HH * DD * DD / 256, 256>>>();
    // K4: apply q-softmax -> fp16 midT
    k_applyq<<<dim3(SS / 256, HH, BB), 256>>>();
    // K5: fused out-proj + bias + rms-norm
    k_ogemm<<<dim3(SS / 64, BB), 512, SMEM_G5>>>(woh_p, mh_p, out, b_out, gamma2);
}

// round 6
// speedup vs baseline: 7.9979x; 1.3555x over previous
#include <cuda_runtime.h>
#include <cuda_fp16.h>
#include <math.h>
#include <cstdint>

#define BB 16
#define CC 512
#define SS 4096
#define HH 8
#define DD 64
#define QKV 1536
#define NSTG 3
#define NSEG 16
#define CSEG 256

// ---------------- scratch (static __device__, allocation-free) ----------------
__device__ __half g_wqh[QKV * CC];
__device__ __half g_woh[CC * CC];
__device__ __half g_xh[(size_t)BB * SS * CC];          // 67 MB
__device__ __half g_qkvh[(size_t)BB * QKV * SS];       // 201 MB
__device__ float  g_kmax[BB * 512];
__device__ float  g_ksum[BB * 512];
__device__ float  g_ctxp[NSEG][BB * HH * DD * DD];     // 33.5 MB partial ctxT
__device__ __half g_ctxh[BB * HH * DD * DD];           // 1 MB   ctxT[e][d] fp16 (scaled)
__device__ __half g_qs[(size_t)BB * HH * SS * DD];     // 67 MB  q-softmax^T [bh][n][d]
__device__ __half g_mh[(size_t)BB * SS * CC];          // 67 MB  midT fp16 [b][n][c]

// ---------------- helpers ----------------
__device__ __forceinline__ uint32_t smem_u32(const void* p) {
    uint32_t a;
    asm("{ .reg .u64 t; cvta.to.shared.u64 t, %1; cvt.u32.u64 %0, t; }" : "=r"(a) : "l"(p));
    return a;
}
#define CP_ASYNC(dst, src) \
    asm volatile("cp.async.cg.shared.global [%0], [%1], 16;" :: "r"(dst), "l"(src) : "memory")
#define CP_COMMIT() asm volatile("cp.async.commit_group;" ::: "memory")
#define CP_WAIT(n)  asm volatile("cp.async.wait_group %0;" :: "n"(n) : "memory")
#define LDSM4(R, addr) \
    asm volatile("ldmatrix.sync.aligned.m8n8.x4.shared.b16 {%0,%1,%2,%3}, [%4];" \
        : "=r"((R)[0]), "=r"((R)[1]), "=r"((R)[2]), "=r"((R)[3]) : "r"(addr))

__device__ __forceinline__ void mma16(float* c, const uint32_t* a, const uint32_t* b) {
    asm volatile(
        "mma.sync.aligned.m16n8k16.row.col.f32.f16.f16.f32 "
        "{%0,%1,%2,%3},{%4,%5,%6,%7},{%8,%9},{%0,%1,%2,%3};"
        : "+f"(c[0]), "+f"(c[1]), "+f"(c[2]), "+f"(c[3])
        : "r"(a[0]), "r"(a[1]), "r"(a[2]), "r"(a[3]), "r"(b[0]), "r"(b[1]));
}

// ---------------------------------------------------------------------------
__global__ void k_prep_wq(const float* __restrict__ w, const float* __restrict__ g1) {
    int i = blockIdx.x * 256 + threadIdx.x;
    g_wqh[i] = __float2half_rn(w[i] * g1[i & (CC - 1)]);
}
__global__ void k_prep_wo(const float* __restrict__ w) {
    int i = blockIdx.x * 256 + threadIdx.x;
    g_woh[i] = __float2half_rn(w[i]);
}

// ---------------------------------------------------------------------------
// normT: xh[b][s][c] = fp16(x[b][c][s]*r[b,s])
// ---------------------------------------------------------------------------
__global__ void k_normT(const float* __restrict__ x) {
    extern __shared__ float sm[];
    float* tile = sm;                  // [512][33]
    float* rr = sm + 512 * 33;
    int b = blockIdx.y, s0 = blockIdx.x * 32;
    int t = threadIdx.x;
    const float* xp = x + (size_t)b * CC * SS + s0;

    for (int i = t; i < 512 * 32; i += 256) {
        int c = i >> 5, sl = i & 31;
        tile[c * 33 + sl] = xp[(size_t)c * SS + sl];
    }
    __syncthreads();

    int sl = t >> 3, part = t & 7;
    float acc = 0.f;
    for (int c = part; c < 512; c += 8) {
        float v = tile[c * 33 + sl];
        acc += v * v;
    }
#pragma unroll
    for (int o = 4; o; o >>= 1) acc += __shfl_down_sync(0xFFFFFFFFu, acc, o);
    if (part == 0) rr[sl] = 22.62741699796952f / fmaxf(sqrtf(acc), 1e-12f);
    __syncthreads();

    float rv = rr[sl];
    __half* op = g_xh + ((size_t)b * SS + s0 + sl) * CC;
    for (int c0 = part * 64; c0 < part * 64 + 64; c0 += 8) {
        __half h[8];
#pragma unroll
        for (int j = 0; j < 8; j++) h[j] = __float2half_rn(tile[(c0 + j) * 33 + sl] * rv);
        *(uint4*)(op + c0) = *(uint4*)h;
    }
}

// ---------------------------------------------------------------------------
// K1: fp16 GEMM -> fp16 out.  qkv[b][M,N] = wq[M,K] @ xh[b][N,K]^T
// ---------------------------------------------------------------------------
__global__ __launch_bounds__(256, 2)
void k_hgemm(const __half* __restrict__ A, const __half* __restrict__ Bg,
             __half* __restrict__ Cg, int M, int Ntot, int K,
             size_t strB, size_t strC) {
    extern __shared__ char smc[];
    uint32_t sbase = smem_u32(smc);

    int tid = threadIdx.x, lane = tid & 31, wid = tid >> 5;
    int b = blockIdx.z, m0 = blockIdx.y * 128, n0 = blockIdx.x * 128;
    const __half* Ab = A + (size_t)m0 * K;
    const __half* Bb = Bg + (size_t)b * strB + (size_t)n0 * K;

    const int NC = K / 64;

    auto issue = [&](int kc, int buf) {
        const __half* Asrc = Ab + kc * 64;
        const __half* Bsrc = Bb + kc * 64;
        uint32_t base = sbase + buf * 32768;
#pragma unroll
        for (int it = 0; it < 4; it++) {
            int id = it * 256 + tid;
            int row = id >> 3, j = id & 7;
            uint32_t dst = base + row * 128 + ((j ^ (row & 7)) << 4);
            CP_ASYNC(dst, Asrc + (size_t)row * K + j * 8);
            CP_ASYNC(dst + 16384, Bsrc + (size_t)row * K + j * 8);
        }
    };

#pragma unroll
    for (int s = 0; s < NSTG; s++) { issue(s, s); CP_COMMIT(); }

    int wm = (wid >> 2) * 64, wn = (wid & 3) * 32;
    int rA = wm + (lane & 7) + ((lane >> 3) & 1) * 8;
    int cA = (lane >> 4);
    int rB = wn + (lane & 7) + ((lane >> 4) & 1) * 8;
    int cB = (lane >> 3) & 1;
    int swA = rA & 7, swB = rB & 7;

    float acc[4][4][4] = {};

    for (int kc = 0; kc < NC; kc++) {
        CP_WAIT(NSTG - 1);
        __syncthreads();
        uint32_t bufA = sbase + (kc % NSTG) * 32768;
        uint32_t bufB = bufA + 16384;
#pragma unroll
        for (int ks = 0; ks < 4; ks++) {
            uint32_t a[4][4], bf[2][4];
            uint32_t kchA = ((uint32_t)(ks * 2 + cA) ^ swA) << 4;
            uint32_t kchB = ((uint32_t)(ks * 2 + cB) ^ swB) << 4;
#pragma unroll
            for (int mi = 0; mi < 4; mi++)
                LDSM4(a[mi], bufA + (rA + mi * 16) * 128 + kchA);
#pragma unroll
            for (int p = 0; p < 2; p++)
                LDSM4(bf[p], bufB + (rB + p * 16) * 128 + kchB);
#pragma unroll
            for (int mi = 0; mi < 4; mi++)
#pragma unroll
                for (int ni = 0; ni < 4; ni++)
                    mma16(acc[mi][ni], a[mi], bf[ni >> 1] + (ni & 1) * 2);
        }
        __syncthreads();
        if (kc + NSTG < NC) issue(kc + NSTG, kc % NSTG);
        CP_COMMIT();
    }

    __half* Cd = Cg + (size_t)b * strC;
#pragma unroll
    for (int mi = 0; mi < 4; mi++) {
        int r0 = m0 + wm + mi * 16 + (lane >> 2);
#pragma unroll
        for (int ni = 0; ni < 4; ni++) {
            int c = n0 + wn + (ni >> 1) * 16 + (ni & 1) * 8 + (lane & 3) * 2;
            *(__half2*)(Cd + (size_t)r0 * Ntot + c) =
                __floats2half2_rn(acc[mi][ni][0], acc[mi][ni][1]);
            *(__half2*)(Cd + (size_t)(r0 + 8) * Ntot + c) =
                __floats2half2_rn(acc[mi][ni][2], acc[mi][ni][3]);
        }
    }
}

// ---------------------------------------------------------------------------
// K2: per-row (over n) max & sumexp for k (fp16 source)
// ---------------------------------------------------------------------------
__global__ void k_kstats() {
    int row = blockIdx.x;
    int b = row >> 9, o = row & 511;
    const __half* p = g_qkvh + ((size_t)b * QKV + 512 + o) * SS;
    __shared__ float red[256];
    int t = threadIdx.x;
    float mx = -3.402823466e38f;
    for (int i = t; i < SS; i += 256) mx = fmaxf(mx, __half2float(p[i]));
    red[t] = mx; __syncthreads();
    for (int st = 128; st > 0; st >>= 1) {
        if (t < st) red[t] = fmaxf(red[t], red[t + st]);
        __syncthreads();
    }
    mx = red[0]; __syncthreads();
    float sm = 0.f;
    for (int i = t; i < SS; i += 256) sm += expf(__half2float(p[i]) - mx);
    red[t] = sm; __syncthreads();
    for (int st = 128; st > 0; st >>= 1) {
        if (t < st) red[t] += red[t + st];
        __syncthreads();
    }
    if (t == 0) { g_kmax[row] = mx; g_ksum[row] = red[0]; }
}

// ---------------------------------------------------------------------------
// qsoft: qs[bh][n][d] = fp16(softmax_d(q[b,h,:,n]))   (transposed write)
// ---------------------------------------------------------------------------
__global__ __launch_bounds__(256, 1)
void k_qsoft() {
    int b = blockIdx.z, h = blockIdx.y;
    int n = blockIdx.x * 256 + threadIdx.x;
    const __half* qp = g_qkvh + ((size_t)b * QKV + h * 64) * SS + n;
    float p[64];
    float mx = -3.402823466e38f;
#pragma unroll
    for (int d = 0; d < 64; d++) {
        p[d] = __half2float(qp[(size_t)d * SS]);
        mx = fmaxf(mx, p[d]);
    }
    float sm = 0.f;
#pragma unroll
    for (int d = 0; d < 64; d++) { p[d] = expf(p[d] - mx); sm += p[d]; }
    float sc = 1.f / sm;
    __half* op = g_qs + ((size_t)(b * HH + h) * SS + n) * 64;
#pragma unroll
    for (int d0 = 0; d0 < 64; d0 += 8) {
        __half hh[8];
#pragma unroll
        for (int j = 0; j < 8; j++) hh[j] = __float2half_rn(p[d0 + j] * sc);
        *(uint4*)(op + d0) = *(uint4*)hh;
    }
}

// ---------------------------------------------------------------------------
// ctx_mma: partial ctxT[e][d] = sum_{n in seg} v[e,n] * exp(k[d,n]-mx[d])
// grid (NSEG, HH, BB), 128 threads (4 warps x 16-row bands), fp16 mma.
// smem: A(v) 64x256h = 32KB (cp.async), B(exp k) 32KB (LDG+exp+STS).
// ---------------------------------------------------------------------------
__global__ __launch_bounds__(128, 3)
void k_ctx_mma() {
    extern __shared__ char smc[];
    int seg = blockIdx.x, h = blockIdx.y, b = blockIdx.z;
    int n0 = seg * CSEG;
    const __half* vp = g_qkvh + ((size_t)b * QKV + 1024 + h * 64) * SS + n0;
    const __half* kp = g_qkvh + ((size_t)b * QKV + 512 + h * 64) * SS + n0;
    const float* mxp = g_kmax + b * 512 + h * 64;

    uint32_t sA = smem_u32(smc), sB = sA + 32768;
    int tid = threadIdx.x, lane = tid & 31, wid = tid >> 5;

    // A = v via cp.async (swizzled 512B rows, 32 chunks)
#pragma unroll
    for (int it = 0; it < 16; it++) {
        int id = it * 128 + tid;
        int row = id >> 5, j = id & 31;
        CP_ASYNC(sA + row * 512 + (((uint32_t)(j ^ (row & 7))) << 4),
                 vp + (size_t)row * SS + j * 8);
    }
    CP_COMMIT();

    // B = exp(k - mx) via LDG + transform + STS
#pragma unroll
    for (int it = 0; it < 16; it++) {
        int id = it * 128 + tid;
        int row = id >> 5, j = id & 31;
        uint4 raw = *(const uint4*)(kp + (size_t)row * SS + j * 8);
        float m = mxp[row];
        const __half* hk = (const __half*)&raw;
        __half hh[8];
#pragma unroll
        for (int q = 0; q < 8; q++)
            hh[q] = __float2half_rn(expf(__half2float(hk[q]) - m));
        *(uint4*)(smc + 32768 + row * 512 + ((uint32_t)(j ^ (row & 7)) << 4)) = *(uint4*)hh;
    }
    CP_WAIT(0);
    __syncthreads();

    int rA = wid * 16 + (lane & 7) + ((lane >> 3) & 1) * 8;
    int cA = lane >> 4;
    int rB = (lane & 7) + ((lane >> 4) & 1) * 8;
    int cB = (lane >> 3) & 1;
    int swA = rA & 7, swB = rB & 7;

    float acc[8][4] = {};
#pragma unroll
    for (int ks = 0; ks < 16; ks++) {
        uint32_t a[4], bf[4][4];
        LDSM4(a, sA + rA * 512 + (((uint32_t)(ks * 2 + cA) ^ swA) << 4));
#pragma unroll
        for (int p = 0; p < 4; p++)
            LDSM4(bf[p], sB + (rB + p * 16) * 512 + (((uint32_t)(ks * 2 + cB) ^ swB) << 4));
#pragma unroll
        for (int p = 0; p < 4; p++)
#pragma unroll
            for (int hf = 0; hf < 2; hf++)
                mma16(acc[p * 2 + hf], a, bf[p] + hf * 2);
    }

    float* cp = g_ctxp[seg] + (size_t)(b * HH + h) * 4096;
    int r0 = wid * 16 + (lane >> 2);
#pragma unroll
    for (int ni = 0; ni < 8; ni++) {
        int d = (ni >> 1) * 16 + (ni & 1) * 8 + (lane & 3) * 2;
        *(float2*)(cp + r0 * 64 + d) = make_float2(acc[ni][0], acc[ni][1]);
        *(float2*)(cp + (r0 + 8) * 64 + d) = make_float2(acc[ni][2], acc[ni][3]);
    }
}

// ---------------------------------------------------------------------------
// ctx finish: ctxh[bh][e][d] = fp16( 0.125/ksum[d] * sum_seg ctxp )
// ---------------------------------------------------------------------------
__global__ void k_ctx_fin() {
    int i = blockIdx.x * 256 + threadIdx.x;        // over BB*HH*4096
    int bh = i >> 12, d = i & 63;
    float s = 0.f;
#pragma unroll
    for (int p = 0; p < NSEG; p++) s += g_ctxp[p][i];
    float inv = 0.125f / g_ksum[(bh >> 3) * 512 + (bh & 7) * 64 + d];
    g_ctxh[i] = __float2half_rn(s * inv);
}

// ---------------------------------------------------------------------------
// apply_mma: mh[b][n][h*64+e] = sum_d qs[bh][n][d] * ctxh[bh][e][d]
// grid (SS/128, HH, BB), 256 threads, M=128 N=64 K=64, single-shot mma.
// ---------------------------------------------------------------------------
__global__ __launch_bounds__(256, 2)
void k_apply_mma() {
    __shared__ __align__(16) char smc[24576];      // A 16KB + B 8KB
    int nt = blockIdx.x, h = blockIdx.y, b = blockIdx.z;
    int n0 = nt * 128;
    const __half* Aq = g_qs + ((size_t)(b * HH + h) * SS + n0) * 64;
    const __half* Bc = g_ctxh + (size_t)(b * HH + h) * 4096;

    uint32_t sA = smem_u32(smc), sB = sA + 16384;
    int tid = threadIdx.x, lane = tid & 31, wid = tid >> 5;

#pragma unroll
    for (int it = 0; it < 4; it++) {
        int id = it * 256 + tid;                   // 1024 chunks A
        int row = id >> 3, j = id & 7;
        CP_ASYNC(sA + row * 128 + ((uint32_t)(j ^ (row & 7)) << 4),
                 Aq + (size_t)row * 64 + j * 8);
    }
#pragma unroll
    for (int it = 0; it < 2; it++) {
        int id = it * 256 + tid;                   // 512 chunks B
        int row = id >> 3, j = id & 7;
        CP_ASYNC(sB + row * 128 + ((uint32_t)(j ^ (row & 7)) << 4),
                 Bc + (size_t)row * 64 + j * 8);
    }
    CP_COMMIT();
    CP_WAIT(0);
    __syncthreads();

    int wm = (wid >> 1) * 32, wn = (wid & 1) * 32;
    int rA = wm + (lane & 7) + ((lane >> 3) & 1) * 8;
    int cA = lane >> 4;
    int rB = wn + (lane & 7) + ((lane >> 4) & 1) * 8;
    int cB = (lane >> 3) & 1;
    int swA = rA & 7, swB = rB & 7;

    float acc[2][4][4] = {};
#pragma unroll
    for (int ks = 0; ks < 4; ks++) {
        uint32_t a[2][4], bf[2][4];
        uint32_t kchA = ((uint32_t)(ks * 2 + cA) ^ swA) << 4;
        uint32_t kchB = ((uint32_t)(ks * 2 + cB) ^ swB) << 4;
#pragma unroll
        for (int mi = 0; mi < 2; mi++)
            LDSM4(a[mi], sA + (rA + mi * 16) * 128 + kchA);
#pragma unroll
        for (int p = 0; p < 2; p++)
            LDSM4(bf[p], sB + (rB + p * 16) * 128 + kchB);
#pragma unroll
        for (int mi = 0; mi < 2; mi++)
#pragma unroll
            for (int ni = 0; ni < 4; ni++)
                mma16(acc[mi][ni], a[mi], bf[ni >> 1] + (ni & 1) * 2);
    }

    __half* outp = g_mh + (size_t)b * SS * CC;
#pragma unroll
    for (int mi = 0; mi < 2; mi++) {
        int r = n0 + wm + mi * 16 + (lane >> 2);
#pragma unroll
        for (int ni = 0; ni < 4; ni++) {
            int c = h * 64 + wn + (ni >> 1) * 16 + (ni & 1) * 8 + (lane & 3) * 2;
            *(__half2*)(outp + (size_t)r * CC + c) =
                __floats2half2_rn(acc[mi][ni][0], acc[mi][ni][1]);
            *(__half2*)(outp + (size_t)(r + 8) * CC + c) =
                __floats2half2_rn(acc[mi][ni][2], acc[mi][ni][3]);
        }
    }
}

// ---------------------------------------------------------------------------
// K5: out = rmsnorm( wo @ mh^T + bias ) * gamma2  (tall 512x64 tile, fused)
// ---------------------------------------------------------------------------
__global__ __launch_bounds__(512, 1)
void k_ogemm(const __half* __restrict__ A, const __half* __restrict__ Bg,
             float* __restrict__ out, const float* __restrict__ bias,
             const float* __restrict__ gamma2) {
    extern __shared__ char smc[];
    const int STG = 36864;
    uint32_t sbase = smem_u32(smc);
    float* colsq = (float*)(smc + 3 * STG);
    float* csc   = colsq + 64;

    int tid = threadIdx.x, lane = tid & 31, wid = tid >> 5;
    int b = blockIdx.y, n0 = blockIdx.x * 64;
    const __half* Bb = Bg + ((size_t)b * SS + n0) * CC;

    if (tid < 64) colsq[tid] = 0.f;

    auto issue = [&](int kc, int buf) {
        uint32_t base = sbase + buf * STG;
#pragma unroll
        for (int it = 0; it < 4; it++) {
            int id = it * 512 + tid;
            int row = id >> 2, j = id & 3;
            uint32_t dst = base + row * 64 + (((uint32_t)j ^ ((row >> 1) & 3)) << 4);
            CP_ASYNC(dst, A + (size_t)row * CC + kc * 32 + j * 8);
        }
        if (tid < 256) {
            int row = tid >> 2, j = tid & 3;
            uint32_t dst = base + 32768 + row * 64 + (((uint32_t)j ^ ((row >> 1) & 3)) << 4);
            CP_ASYNC(dst, Bb + (size_t)row * CC + kc * 32 + j * 8);
        }
    };

#pragma unroll
    for (int s = 0; s < NSTG; s++) { issue(s, s); CP_COMMIT(); }

    int wm = (wid >> 1) * 64, wn = (wid & 1) * 32;
    int rA = wm + (lane & 7) + ((lane >> 3) & 1) * 8;
    int cA = (lane >> 4);
    int rB = wn + (lane & 7) + ((lane >> 4) & 1) * 8;
    int cB = (lane >> 3) & 1;
    int swA = (rA >> 1) & 3, swB = (rB >> 1) & 3;

    float acc[4][4][4] = {};
    const int NC = CC / 32;

    for (int kc = 0; kc < NC; kc++) {
        CP_WAIT(NSTG - 1);
        __syncthreads();
        uint32_t bufA = sbase + (kc % NSTG) * STG;
        uint32_t bufB = bufA + 32768;
#pragma unroll
        for (int ks = 0; ks < 2; ks++) {
            uint32_t a[4][4], bf[2][4];
            uint32_t kchA = ((uint32_t)(ks * 2 + cA) ^ swA) << 4;
            uint32_t kchB = ((uint32_t)(ks * 2 + cB) ^ swB) << 4;
#pragma unroll
            for (int mi = 0; mi < 4; mi++)
                LDSM4(a[mi], bufA + (rA + mi * 16) * 64 + kchA);
#pragma unroll
            for (int p = 0; p < 2; p++)
                LDSM4(bf[p], bufB + (rB + p * 16) * 64 + kchB);
#pragma unroll
            for (int mi = 0; mi < 4; mi++)
#pragma unroll
                for (int ni = 0; ni < 4; ni++)
                    mma16(acc[mi][ni], a[mi], bf[ni >> 1] + (ni & 1) * 2);
        }
        __syncthreads();
        if (kc + NSTG < NC) issue(kc + NSTG, kc % NSTG);
        CP_COMMIT();
    }

    float bi0[4], bi1[4];
#pragma unroll
    for (int mi = 0; mi < 4; mi++) {
        bi0[mi] = bias[wm + mi * 16 + (lane >> 2)];
        bi1[mi] = bias[wm + mi * 16 + (lane >> 2) + 8];
    }
#pragma unroll
    for (int ni = 0; ni < 4; ni++) {
        float l0 = 0.f, l1 = 0.f;
#pragma unroll
        for (int mi = 0; mi < 4; mi++) {
            acc[mi][ni][0] += bi0[mi]; acc[mi][ni][1] += bi0[mi];
            acc[mi][ni][2] += bi1[mi]; acc[mi][ni][3] += bi1[mi];
            l0 += acc[mi][ni][0] * acc[mi][ni][0] + acc[mi][ni][2] * acc[mi][ni][2];
            l1 += acc[mi][ni][1] * acc[mi][ni][1] + acc[mi][ni][3] * acc[mi][ni][3];
        }
#pragma unroll
        for (int o = 4; o <= 16; o <<= 1) {
            l0 += __shfl_xor_sync(0xFFFFFFFFu, l0, o);
            l1 += __shfl_xor_sync(0xFFFFFFFFu, l1, o);
        }
        if ((lane >> 2) == 0) {
            int cloc = wn + (ni >> 1) * 16 + (ni & 1) * 8 + (lane & 3) * 2;
            atomicAdd(colsq + cloc, l0);
            atomicAdd(colsq + cloc + 1, l1);
        }
    }
    __syncthreads();
    if (tid < 64)
        csc[tid] = 22.62741699796952f / fmaxf(sqrtf(colsq[tid]), 1e-12f);
    __syncthreads();

    float* Cd = out + (size_t)b * CC * SS + n0;
#pragma unroll
    for (int mi = 0; mi < 4; mi++) {
        int r0 = wm + mi * 16 + (lane >> 2);
        float g0 = gamma2[r0], g1 = gamma2[r0 + 8];
#pragma unroll
        for (int ni = 0; ni < 4; ni++) {
            int cloc = wn + (ni >> 1) * 16 + (ni & 1) * 8 + (lane & 3) * 2;
            float s0 = csc[cloc], s1 = csc[cloc + 1];
            *(float2*)(Cd + (size_t)r0 * SS + cloc) =
                make_float2(acc[mi][ni][0] * s0 * g0, acc[mi][ni][1] * s1 * g0);
            *(float2*)(Cd + (size_t)(r0 + 8) * SS + cloc) =
                make_float2(acc[mi][ni][2] * s0 * g1, acc[mi][ni][3] * s1 * g1);
        }
    }
}

// ---------------------------------------------------------------------------
extern "C" void kernel_launch(void* const* d_in, const int* in_sizes, int n_in,
                              void* d_out, int out_size) {
    const float* x      = (const float*)d_in[0];
    const float* gamma1 = (const float*)d_in[1];
    const float* w_qkv  = (const float*)d_in[2];
    const float* w_out  = (const float*)d_in[3];
    const float* b_out  = (const float*)d_in[4];
    const float* gamma2 = (const float*)d_in[5];
    float* out = (float*)d_out;

    __half *wqh_p, *woh_p, *xh_p, *mh_p, *qkvh_p;
    cudaGetSymbolAddress((void**)&wqh_p,  g_wqh);
    cudaGetSymbolAddress((void**)&woh_p,  g_woh);
    cudaGetSymbolAddress((void**)&xh_p,   g_xh);
    cudaGetSymbolAddress((void**)&mh_p,   g_mh);
    cudaGetSymbolAddress((void**)&qkvh_p, g_qkvh);

    const int SMEM_NT = (512 * 33 + 32) * 4;
    const int SMEM_G1 = NSTG * 32768;
    const int SMEM_CX = 65536;
    const int SMEM_G5 = NSTG * 36864 + 512;
    cudaFuncSetAttribute(k_normT,   cudaFuncAttributeMaxDynamicSharedMemorySize, SMEM_NT);
    cudaFuncSetAttribute(k_hgemm,   cudaFuncAttributeMaxDynamicSharedMemorySize, SMEM_G1);
    cudaFuncSetAttribute(k_ctx_mma, cudaFuncAttributeMaxDynamicSharedMemorySize, SMEM_CX);
    cudaFuncSetAttribute(k_ogemm,   cudaFuncAttributeMaxDynamicSharedMemorySize, SMEM_G5);

    k_prep_wq<<<QKV * CC / 256, 256>>>(w_qkv, gamma1);
    k_prep_wo<<<CC * CC / 256, 256>>>(w_out);
    k_normT<<<dim3(SS / 32, BB), 256, SMEM_NT>>>(x);
    // K1: qkv (fp16)
    k_hgemm<<<dim3(SS / 128, QKV / 128, BB), 256, SMEM_G1>>>(
        wqh_p, xh_p, qkvh_p, QKV, SS, CC, (size_t)SS * CC, (size_t)QKV * SS);
    // K2: k stats
    k_kstats<<<BB * 512, 256>>>();
    // q softmax (transposed fp16)
    k_qsoft<<<dim3(SS / 256, HH, BB), 256>>>();
    // ctx via tensor cores (split-K partials) + finish
    k_ctx_mma<<<dim3(NSEG, HH, BB), 128, SMEM_CX>>>();
    k_ctx_fin<<<BB * HH * 4096 / 256, 256>>>();
    // apply q to ctx via tensor cores -> mh
    k_apply_mma<<<dim3(SS / 128, HH, BB), 256>>>();
    // K5: fused out-proj + bias + rms-norm
    k_ogemm<<<dim3(SS / 64, BB), 512, SMEM_G5>>>(woh_p, mh_p, out, b_out, gamma2);
}

// round 7
// speedup vs baseline: 9.4246x; 1.1784x over previous
#include <cuda_runtime.h>
#include <cuda_fp16.h>
#include <math.h>
#include <cstdint>

#define BB 16
#define CC 512
#define SS 4096
#define HH 8
#define DD 64
#define QKV 1536
#define NSTG 3
#define NSEG 16
#define CSEG 256

// ---------------- scratch (static __device__, allocation-free) ----------------
__device__ __half g_wqh[QKV * CC];
__device__ __half g_woh[CC * CC];
__device__ __half g_xh[(size_t)BB * SS * CC];          // 67 MB
__device__ __half g_qkvh[(size_t)BB * QKV * SS];       // 201 MB
__device__ __half g_ekh[(size_t)BB * 512 * SS];        // 67 MB  exp(k) fp16
__device__ float  g_ksum[BB * 512];
__device__ float  g_ctxp[NSEG][BB * HH * DD * DD];     // partial ctxT
__device__ __half g_ctxh[BB * HH * DD * DD];           // ctxT[e][d] fp16 scaled
__device__ __half g_qs[(size_t)BB * HH * SS * DD];     // 67 MB q-softmax^T
__device__ __half g_mh[(size_t)BB * SS * CC];          // 67 MB midT fp16

// ---------------- helpers ----------------
__device__ __forceinline__ uint32_t smem_u32(const void* p) {
    uint32_t a;
    asm("{ .reg .u64 t; cvta.to.shared.u64 t, %1; cvt.u32.u64 %0, t; }" : "=r"(a) : "l"(p));
    return a;
}
#define CP_ASYNC(dst, src) \
    asm volatile("cp.async.cg.shared.global [%0], [%1], 16;" :: "r"(dst), "l"(src) : "memory")
#define CP_COMMIT() asm volatile("cp.async.commit_group;" ::: "memory")
#define CP_WAIT(n)  asm volatile("cp.async.wait_group %0;" :: "n"(n) : "memory")
#define LDSM4(R, addr) \
    asm volatile("ldmatrix.sync.aligned.m8n8.x4.shared.b16 {%0,%1,%2,%3}, [%4];" \
        : "=r"((R)[0]), "=r"((R)[1]), "=r"((R)[2]), "=r"((R)[3]) : "r"(addr))

__device__ __forceinline__ void mma16(float* c, const uint32_t* a, const uint32_t* b) {
    asm volatile(
        "mma.sync.aligned.m16n8k16.row.col.f32.f16.f16.f32 "
        "{%0,%1,%2,%3},{%4,%5,%6,%7},{%8,%9},{%0,%1,%2,%3};"
        : "+f"(c[0]), "+f"(c[1]), "+f"(c[2]), "+f"(c[3])
        : "r"(a[0]), "r"(a[1]), "r"(a[2]), "r"(a[3]), "r"(b[0]), "r"(b[1]));
}

// ---------------------------------------------------------------------------
__global__ void k_prep_wq(const float* __restrict__ w, const float* __restrict__ g1) {
    int i = blockIdx.x * 256 + threadIdx.x;
    g_wqh[i] = __float2half_rn(w[i] * g1[i & (CC - 1)]);
}
__global__ void k_prep_wo(const float* __restrict__ w) {
    int i = blockIdx.x * 256 + threadIdx.x;
    g_woh[i] = __float2half_rn(w[i]);
}

// ---------------------------------------------------------------------------
// normT: xh[b][s][c] = fp16(x[b][c][s]*r[b,s])
// ---------------------------------------------------------------------------
__global__ void k_normT(const float* __restrict__ x) {
    extern __shared__ float sm[];
    float* tile = sm;                  // [512][33]
    float* rr = sm + 512 * 33;
    int b = blockIdx.y, s0 = blockIdx.x * 32;
    int t = threadIdx.x;
    const float* xp = x + (size_t)b * CC * SS + s0;

    for (int i = t; i < 512 * 32; i += 256) {
        int c = i >> 5, sl = i & 31;
        tile[c * 33 + sl] = xp[(size_t)c * SS + sl];
    }
    __syncthreads();

    int sl = t >> 3, part = t & 7;
    float acc = 0.f;
    for (int c = part; c < 512; c += 8) {
        float v = tile[c * 33 + sl];
        acc += v * v;
    }
#pragma unroll
    for (int o = 4; o; o >>= 1) acc += __shfl_down_sync(0xFFFFFFFFu, acc, o);
    if (part == 0) rr[sl] = 22.62741699796952f / fmaxf(sqrtf(acc), 1e-12f);
    __syncthreads();

    float rv = rr[sl];
    __half* op = g_xh + ((size_t)b * SS + s0 + sl) * CC;
    for (int c0 = part * 64; c0 < part * 64 + 64; c0 += 8) {
        __half h[8];
#pragma unroll
        for (int j = 0; j < 8; j++) h[j] = __float2half_rn(tile[(c0 + j) * 33 + sl] * rv);
        *(uint4*)(op + c0) = *(uint4*)h;
    }
}

// ---------------------------------------------------------------------------
// K1: fp16 GEMM -> fp16 out.  qkv[b][M,N] = wq[M,K] @ xh[b][N,K]^T
// single-sync 3-stage pipeline
// ---------------------------------------------------------------------------
__global__ __launch_bounds__(256, 2)
void k_hgemm(const __half* __restrict__ A, const __half* __restrict__ Bg,
             __half* __restrict__ Cg, int M, int Ntot, int K,
             size_t strB, size_t strC) {
    extern __shared__ char smc[];
    uint32_t sbase = smem_u32(smc);

    int tid = threadIdx.x, lane = tid & 31, wid = tid >> 5;
    int b = blockIdx.z, m0 = blockIdx.y * 128, n0 = blockIdx.x * 128;
    const __half* Ab = A + (size_t)m0 * K;
    const __half* Bb = Bg + (size_t)b * strB + (size_t)n0 * K;

    const int NC = K / 64;

    auto issue = [&](int kc, int buf) {
        const __half* Asrc = Ab + kc * 64;
        const __half* Bsrc = Bb + kc * 64;
        uint32_t base = sbase + buf * 32768;
#pragma unroll
        for (int it = 0; it < 4; it++) {
            int id = it * 256 + tid;
            int row = id >> 3, j = id & 7;
            uint32_t dst = base + row * 128 + ((j ^ (row & 7)) << 4);
            CP_ASYNC(dst, Asrc + (size_t)row * K + j * 8);
            CP_ASYNC(dst + 16384, Bsrc + (size_t)row * K + j * 8);
        }
    };

#pragma unroll
    for (int s = 0; s < NSTG - 1; s++) { issue(s, s); CP_COMMIT(); }

    int wm = (wid >> 2) * 64, wn = (wid & 3) * 32;
    int rA = wm + (lane & 7) + ((lane >> 3) & 1) * 8;
    int cA = (lane >> 4);
    int rB = wn + (lane & 7) + ((lane >> 4) & 1) * 8;
    int cB = (lane >> 3) & 1;
    int swA = rA & 7, swB = rB & 7;

    float acc[4][4][4] = {};

    for (int kc = 0; kc < NC; kc++) {
        CP_WAIT(NSTG - 2);
        __syncthreads();
        if (kc + NSTG - 1 < NC) issue(kc + NSTG - 1, (kc + NSTG - 1) % NSTG);
        CP_COMMIT();
        uint32_t bufA = sbase + (kc % NSTG) * 32768;
        uint32_t bufB = bufA + 16384;
#pragma unroll
        for (int ks = 0; ks < 4; ks++) {
            uint32_t a[4][4], bf[2][4];
            uint32_t kchA = ((uint32_t)(ks * 2 + cA) ^ swA) << 4;
            uint32_t kchB = ((uint32_t)(ks * 2 + cB) ^ swB) << 4;
#pragma unroll
            for (int mi = 0; mi < 4; mi++)
                LDSM4(a[mi], bufA + (rA + mi * 16) * 128 + kchA);
#pragma unroll
            for (int p = 0; p < 2; p++)
                LDSM4(bf[p], bufB + (rB + p * 16) * 128 + kchB);
#pragma unroll
            for (int mi = 0; mi < 4; mi++)
#pragma unroll
                for (int ni = 0; ni < 4; ni++)
                    mma16(acc[mi][ni], a[mi], bf[ni >> 1] + (ni & 1) * 2);
        }
    }

    __half* Cd = Cg + (size_t)b * strC;
#pragma unroll
    for (int mi = 0; mi < 4; mi++) {
        int r0 = m0 + wm + mi * 16 + (lane >> 2);
#pragma unroll
        for (int ni = 0; ni < 4; ni++) {
            int c = n0 + wn + (ni >> 1) * 16 + (ni & 1) * 8 + (lane & 3) * 2;
            *(__half2*)(Cd + (size_t)r0 * Ntot + c) =
                __floats2half2_rn(acc[mi][ni][0], acc[mi][ni][1]);
            *(__half2*)(Cd + (size_t)(r0 + 8) * Ntot + c) =
                __floats2half2_rn(acc[mi][ni][2], acc[mi][ni][3]);
        }
    }
}

// ---------------------------------------------------------------------------
// kexp: ek[row][n] = fp16(__expf(k[row][n])); ksum[row] = sum_n  (single pass)
// rows = b*512 + h*64 + d
// ---------------------------------------------------------------------------
__global__ void k_kexp() {
    int row = blockIdx.x;
    int b = row >> 9, o = row & 511;
    const __half* p = g_qkvh + ((size_t)b * QKV + 512 + o) * SS;
    __half* ep = g_ekh + (size_t)row * SS;
    __shared__ float red[8];
    int t = threadIdx.x, lane = t & 31, wid = t >> 5;

    float sm = 0.f;
#pragma unroll
    for (int i0 = 0; i0 < SS; i0 += 2048) {
        int i = i0 + t * 8;
        uint4 raw = *(const uint4*)(p + i);
        const __half* hk = (const __half*)&raw;
        __half hh[8];
#pragma unroll
        for (int j = 0; j < 8; j++) {
            float e = __expf(__half2float(hk[j]));
            sm += e;
            hh[j] = __float2half_rn(e);
        }
        *(uint4*)(ep + i) = *(uint4*)hh;
    }
#pragma unroll
    for (int o2 = 16; o2; o2 >>= 1) sm += __shfl_xor_sync(0xFFFFFFFFu, sm, o2);
    if (lane == 0) red[wid] = sm;
    __syncthreads();
    if (t == 0) {
        float s = 0.f;
#pragma unroll
        for (int w = 0; w < 8; w++) s += red[w];
        g_ksum[row] = s;
    }
}

// ---------------------------------------------------------------------------
// qsoft: qs[bh][n][d] = fp16(softmax_d(q)) (no max shift; __expf)
// ---------------------------------------------------------------------------
__global__ __launch_bounds__(256, 1)
void k_qsoft() {
    int b = blockIdx.z, h = blockIdx.y;
    int n = blockIdx.x * 256 + threadIdx.x;
    const __half* qp = g_qkvh + ((size_t)b * QKV + h * 64) * SS + n;
    float p[64];
    float sm = 0.f;
#pragma unroll
    for (int d = 0; d < 64; d++) {
        p[d] = __expf(__half2float(qp[(size_t)d * SS]));
        sm += p[d];
    }
    float sc = 1.f / sm;
    __half* op = g_qs + ((size_t)(b * HH + h) * SS + n) * 64;
#pragma unroll
    for (int d0 = 0; d0 < 64; d0 += 8) {
        __half hh[8];
#pragma unroll
        for (int j = 0; j < 8; j++) hh[j] = __float2half_rn(p[d0 + j] * sc);
        *(uint4*)(op + d0) = *(uint4*)hh;
    }
}

// ---------------------------------------------------------------------------
// ctx_mma: partial ctxT[e][d] = sum_{n in seg} v[e,n] * ek[d,n]
// grid (NSEG, HH, BB), 128 threads; both tiles pure cp.async.
// ---------------------------------------------------------------------------
__global__ __launch_bounds__(128, 3)
void k_ctx_mma() {
    extern __shared__ char smc[];
    int seg = blockIdx.x, h = blockIdx.y, b = blockIdx.z;
    int n0 = seg * CSEG;
    const __half* vp = g_qkvh + ((size_t)b * QKV + 1024 + h * 64) * SS + n0;
    const __half* ekp = g_ekh + (size_t)(b * 512 + h * 64) * SS + n0;

    uint32_t sA = smem_u32(smc), sB = sA + 32768;
    int tid = threadIdx.x, lane = tid & 31, wid = tid >> 5;

#pragma unroll
    for (int it = 0; it < 16; it++) {
        int id = it * 128 + tid;
        int row = id >> 5, j = id & 31;
        uint32_t soff = row * 512 + (((uint32_t)(j ^ (row & 7))) << 4);
        CP_ASYNC(sA + soff, vp + (size_t)row * SS + j * 8);
        CP_ASYNC(sB + soff, ekp + (size_t)row * SS + j * 8);
    }
    CP_COMMIT();
    CP_WAIT(0);
    __syncthreads();

    int rA = wid * 16 + (lane & 7) + ((lane >> 3) & 1) * 8;
    int cA = lane >> 4;
    int rB = (lane & 7) + ((lane >> 4) & 1) * 8;
    int cB = (lane >> 3) & 1;
    int swA = rA & 7, swB = rB & 7;

    float acc[8][4] = {};
#pragma unroll
    for (int ks = 0; ks < 16; ks++) {
        uint32_t a[4], bf[4][4];
        LDSM4(a, sA + rA * 512 + (((uint32_t)(ks * 2 + cA) ^ swA) << 4));
#pragma unroll
        for (int p = 0; p < 4; p++)
            LDSM4(bf[p], sB + (rB + p * 16) * 512 + (((uint32_t)(ks * 2 + cB) ^ swB) << 4));
#pragma unroll
        for (int p = 0; p < 4; p++)
#pragma unroll
            for (int hf = 0; hf < 2; hf++)
                mma16(acc[p * 2 + hf], a, bf[p] + hf * 2);
    }

    float* cp = g_ctxp[seg] + (size_t)(b * HH + h) * 4096;
    int r0 = wid * 16 + (lane >> 2);
#pragma unroll
    for (int ni = 0; ni < 8; ni++) {
        int d = (ni >> 1) * 16 + (ni & 1) * 8 + (lane & 3) * 2;
        *(float2*)(cp + r0 * 64 + d) = make_float2(acc[ni][0], acc[ni][1]);
        *(float2*)(cp + (r0 + 8) * 64 + d) = make_float2(acc[ni][2], acc[ni][3]);
    }
}

// ---------------------------------------------------------------------------
// ctx finish: ctxh[bh][e][d] = fp16( 0.125/ksum[d] * sum_seg ctxp )
// ---------------------------------------------------------------------------
__global__ void k_ctx_fin() {
    int i = blockIdx.x * 256 + threadIdx.x;
    int bh = i >> 12, d = i & 63;
    float s = 0.f;
#pragma unroll
    for (int p = 0; p < NSEG; p++) s += g_ctxp[p][i];
    float inv = 0.125f / g_ksum[(bh >> 3) * 512 + (bh & 7) * 64 + d];
    g_ctxh[i] = __float2half_rn(s * inv);
}

// ---------------------------------------------------------------------------
// apply_mma: mh[b][n][h*64+e] = sum_d qs[bh][n][d] * ctxh[bh][e][d]
// ---------------------------------------------------------------------------
__global__ __launch_bounds__(256, 2)
void k_apply_mma() {
    __shared__ __align__(16) char smc[24576];
    int nt = blockIdx.x, h = blockIdx.y, b = blockIdx.z;
    int n0 = nt * 128;
    const __half* Aq = g_qs + ((size_t)(b * HH + h) * SS + n0) * 64;
    const __half* Bc = g_ctxh + (size_t)(b * HH + h) * 4096;

    uint32_t sA = smem_u32(smc), sB = sA + 16384;
    int tid = threadIdx.x, lane = tid & 31, wid = tid >> 5;

#pragma unroll
    for (int it = 0; it < 4; it++) {
        int id = it * 256 + tid;
        int row = id >> 3, j = id & 7;
        CP_ASYNC(sA + row * 128 + ((uint32_t)(j ^ (row & 7)) << 4),
                 Aq + (size_t)row * 64 + j * 8);
    }
#pragma unroll
    for (int it = 0; it < 2; it++) {
        int id = it * 256 + tid;
        int row = id >> 3, j = id & 7;
        CP_ASYNC(sB + row * 128 + ((uint32_t)(j ^ (row & 7)) << 4),
                 Bc + (size_t)row * 64 + j * 8);
    }
    CP_COMMIT();
    CP_WAIT(0);
    __syncthreads();

    int wm = (wid >> 1) * 32, wn = (wid & 1) * 32;
    int rA = wm + (lane & 7) + ((lane >> 3) & 1) * 8;
    int cA = lane >> 4;
    int rB = wn + (lane & 7) + ((lane >> 4) & 1) * 8;
    int cB = (lane >> 3) & 1;
    int swA = rA & 7, swB = rB & 7;

    float acc[2][4][4] = {};
#pragma unroll
    for (int ks = 0; ks < 4; ks++) {
        uint32_t a[2][4], bf[2][4];
        uint32_t kchA = ((uint32_t)(ks * 2 + cA) ^ swA) << 4;
        uint32_t kchB = ((uint32_t)(ks * 2 + cB) ^ swB) << 4;
#pragma unroll
        for (int mi = 0; mi < 2; mi++)
            LDSM4(a[mi], sA + (rA + mi * 16) * 128 + kchA);
#pragma unroll
        for (int p = 0; p < 2; p++)
            LDSM4(bf[p], sB + (rB + p * 16) * 128 + kchB);
#pragma unroll
        for (int mi = 0; mi < 2; mi++)
#pragma unroll
            for (int ni = 0; ni < 4; ni++)
                mma16(acc[mi][ni], a[mi], bf[ni >> 1] + (ni & 1) * 2);
    }

    __half* outp = g_mh + (size_t)b * SS * CC;
#pragma unroll
    for (int mi = 0; mi < 2; mi++) {
        int r = n0 + wm + mi * 16 + (lane >> 2);
#pragma unroll
        for (int ni = 0; ni < 4; ni++) {
            int c = h * 64 + wn + (ni >> 1) * 16 + (ni & 1) * 8 + (lane & 3) * 2;
            *(__half2*)(outp + (size_t)r * CC + c) =
                __floats2half2_rn(acc[mi][ni][0], acc[mi][ni][1]);
            *(__half2*)(outp + (size_t)(r + 8) * CC + c) =
                __floats2half2_rn(acc[mi][ni][2], acc[mi][ni][3]);
        }
    }
}

// ---------------------------------------------------------------------------
// K5: out = rmsnorm( wo @ mh^T + bias ) * gamma2   (single-sync pipeline)
// ---------------------------------------------------------------------------
__global__ __launch_bounds__(512, 1)
void k_ogemm(const __half* __restrict__ A, const __half* __restrict__ Bg,
             float* __restrict__ out, const float* __restrict__ bias,
             const float* __restrict__ gamma2) {
    extern __shared__ char smc[];
    const int STG = 36864;
    uint32_t sbase = smem_u32(smc);
    float* colsq = (float*)(smc + 3 * STG);
    float* csc   = colsq + 64;

    int tid = threadIdx.x, lane = tid & 31, wid = tid >> 5;
    int b = blockIdx.y, n0 = blockIdx.x * 64;
    const __half* Bb = Bg + ((size_t)b * SS + n0) * CC;

    if (tid < 64) colsq[tid] = 0.f;

    auto issue = [&](int kc, int buf) {
        uint32_t base = sbase + buf * STG;
#pragma unroll
        for (int it = 0; it < 4; it++) {
            int id = it * 512 + tid;
            int row = id >> 2, j = id & 3;
            uint32_t dst = base + row * 64 + (((uint32_t)j ^ ((row >> 1) & 3)) << 4);
            CP_ASYNC(dst, A + (size_t)row * CC + kc * 32 + j * 8);
        }
        if (tid < 256) {
            int row = tid >> 2, j = tid & 3;
            uint32_t dst = base + 32768 + row * 64 + (((uint32_t)j ^ ((row >> 1) & 3)) << 4);
            CP_ASYNC(dst, Bb + (size_t)row * CC + kc * 32 + j * 8);
        }
    };

#pragma unroll
    for (int s = 0; s < NSTG - 1; s++) { issue(s, s); CP_COMMIT(); }

    int wm = (wid >> 1) * 64, wn = (wid & 1) * 32;
    int rA = wm + (lane & 7) + ((lane >> 3) & 1) * 8;
    int cA = (lane >> 4);
    int rB = wn + (lane & 7) + ((lane >> 4) & 1) * 8;
    int cB = (lane >> 3) & 1;
    int swA = (rA >> 1) & 3, swB = (rB >> 1) & 3;

    float acc[4][4][4] = {};
    const int NC = CC / 32;

    for (int kc = 0; kc < NC; kc++) {
        CP_WAIT(NSTG - 2);
        __syncthreads();
        if (kc + NSTG - 1 < NC) issue(kc + NSTG - 1, (kc + NSTG - 1) % NSTG);
        CP_COMMIT();
        uint32_t bufA = sbase + (kc % NSTG) * STG;
        uint32_t bufB = bufA + 32768;
#pragma unroll
        for (int ks = 0; ks < 2; ks++) {
            uint32_t a[4][4], bf[2][4];
            uint32_t kchA = ((uint32_t)(ks * 2 + cA) ^ swA) << 4;
            uint32_t kchB = ((uint32_t)(ks * 2 + cB) ^ swB) << 4;
#pragma unroll
            for (int mi = 0; mi < 4; mi++)
                LDSM4(a[mi], bufA + (rA + mi * 16) * 64 + kchA);
#pragma unroll
            for (int p = 0; p < 2; p++)
                LDSM4(bf[p], bufB + (rB + p * 16) * 64 + kchB);
#pragma unroll
            for (int mi = 0; mi < 4; mi++)
#pragma unroll
                for (int ni = 0; ni < 4; ni++)
                    mma16(acc[mi][ni], a[mi], bf[ni >> 1] + (ni & 1) * 2);
        }
    }

    float bi0[4], bi1[4];
#pragma unroll
    for (int mi = 0; mi < 4; mi++) {
        bi0[mi] = bias[wm + mi * 16 + (lane >> 2)];
        bi1[mi] = bias[wm + mi * 16 + (lane >> 2) + 8];
    }
#pragma unroll
    for (int ni = 0; ni < 4; ni++) {
        float l0 = 0.f, l1 = 0.f;
#pragma unroll
        for (int mi = 0; mi < 4; mi++) {
            acc[mi][ni][0] += bi0[mi]; acc[mi][ni][1] += bi0[mi];
            acc[mi][ni][2] += bi1[mi]; acc[mi][ni][3] += bi1[mi];
            l0 += acc[mi][ni][0] * acc[mi][ni][0] + acc[mi][ni][2] * acc[mi][ni][2];
            l1 += acc[mi][ni][1] * acc[mi][ni][1] + acc[mi][ni][3] * acc[mi][ni][3];
        }
#pragma unroll
        for (int o = 4; o <= 16; o <<= 1) {
            l0 += __shfl_xor_sync(0xFFFFFFFFu, l0, o);
            l1 += __shfl_xor_sync(0xFFFFFFFFu, l1, o);
        }
        if ((lane >> 2) == 0) {
            int cloc = wn + (ni >> 1) * 16 + (ni & 1) * 8 + (lane & 3) * 2;
            atomicAdd(colsq + cloc, l0);
            atomicAdd(colsq + cloc + 1, l1);
        }
    }
    __syncthreads();
    if (tid < 64)
        csc[tid] = 22.62741699796952f / fmaxf(sqrtf(colsq[tid]), 1e-12f);
    __syncthreads();

    float* Cd = out + (size_t)b * CC * SS + n0;
#pragma unroll
    for (int mi = 0; mi < 4; mi++) {
        int r0 = wm + mi * 16 + (lane >> 2);
        float g0 = gamma2[r0], g1 = gamma2[r0 + 8];
#pragma unroll
        for (int ni = 0; ni < 4; ni++) {
            int cloc = wn + (ni >> 1) * 16 + (ni & 1) * 8 + (lane & 3) * 2;
            float s0 = csc[cloc], s1 = csc[cloc + 1];
            *(float2*)(Cd + (size_t)r0 * SS + cloc) =
                make_float2(acc[mi][ni][0] * s0 * g0, acc[mi][ni][1] * s1 * g0);
            *(float2*)(Cd + (size_t)(r0 + 8) * SS + cloc) =
                make_float2(acc[mi][ni][2] * s0 * g1, acc[mi][ni][3] * s1 * g1);
        }
    }
}

// ---------------------------------------------------------------------------
extern "C" void kernel_launch(void* const* d_in, const int* in_sizes, int n_in,
                              void* d_out, int out_size) {
    const float* x      = (const float*)d_in[0];
    const float* gamma1 = (const float*)d_in[1];
    const float* w_qkv  = (const float*)d_in[2];
    const float* w_out  = (const float*)d_in[3];
    const float* b_out  = (const float*)d_in[4];
    const float* gamma2 = (const float*)d_in[5];
    float* out = (float*)d_out;

    __half *wqh_p, *woh_p, *xh_p, *mh_p, *qkvh_p;
    cudaGetSymbolAddress((void**)&wqh_p,  g_wqh);
    cudaGetSymbolAddress((void**)&woh_p,  g_woh);
    cudaGetSymbolAddress((void**)&xh_p,   g_xh);
    cudaGetSymbolAddress((void**)&mh_p,   g_mh);
    cudaGetSymbolAddress((void**)&qkvh_p, g_qkvh);

    const int SMEM_NT = (512 * 33 + 32) * 4;
    const int SMEM_G1 = NSTG * 32768;
    const int SMEM_CX = 65536;
    const int SMEM_G5 = NSTG * 36864 + 512;
    cudaFuncSetAttribute(k_normT,   cudaFuncAttributeMaxDynamicSharedMemorySize, SMEM_NT);
    cudaFuncSetAttribute(k_hgemm,   cudaFuncAttributeMaxDynamicSharedMemorySize, SMEM_G1);
    cudaFuncSetAttribute(k_ctx_mma, cudaFuncAttributeMaxDynamicSharedMemorySize, SMEM_CX);
    cudaFuncSetAttribute(k_ogemm,   cudaFuncAttributeMaxDynamicSharedMemorySize, SMEM_G5);

    k_prep_wq<<<QKV * CC / 256, 256>>>(w_qkv, gamma1);
    k_prep_wo<<<CC * CC / 256, 256>>>(w_out);
    k_normT<<<dim3(SS / 32, BB), 256, SMEM_NT>>>(x);
    // K1: qkv (fp16)
    k_hgemm<<<dim3(SS / 128, QKV / 128, BB), 256, SMEM_G1>>>(
        wqh_p, xh_p, qkvh_p, QKV, SS, CC, (size_t)SS * CC, (size_t)QKV * SS);
    // exp(k) + row sums (single pass)
    k_kexp<<<BB * 512, 256>>>();
    // q softmax (transposed fp16)
    k_qsoft<<<dim3(SS / 256, HH, BB), 256>>>();
    // ctx via tensor cores + finish
    k_ctx_mma<<<dim3(NSEG, HH, BB), 128, SMEM_CX>>>();
    k_ctx_fin<<<BB * HH * 4096 / 256, 256>>>();
    // apply q to ctx -> mh
    k_apply_mma<<<dim3(SS / 128, HH, BB), 256>>>();
    // K5: fused out-proj + bias + rms-norm
    k_ogemm<<<dim3(SS / 64, BB), 512, SMEM_G5>>>(woh_p, mh_p, out, b_out, gamma2);
}

// round 9
// speedup vs baseline: 9.7168x; 1.0310x over previous
#include <cuda_runtime.h>
#include <cuda_fp16.h>
#include <math.h>
#include <cstdint>

#define BB 16
#define CC 512
#define SS 4096
#define HH 8
#define DD 64
#define QKV 1536
#define NSTG 3
#define NSEG 16
#define CSEG 256

// ---------------- scratch (static __device__, allocation-free) ----------------
__device__ __half g_wqh[QKV * CC];
__device__ __half g_woh[CC * CC];
__device__ __half g_xh[(size_t)BB * SS * CC];          // 67 MB
__device__ __half g_qkvh[(size_t)BB * QKV * SS];       // v region used
__device__ __half g_ekh[(size_t)BB * 512 * SS];        // 67 MB  exp(k) fp16
__device__ float  g_ksump[128][BB * 512];              // 4 MB   k row-sum partials
__device__ float  g_ksum[BB * 512];
__device__ float  g_qsum[(size_t)BB * HH * SS];        // 2 MB   q col sums (per n)
__device__ float  g_ctxp[NSEG][BB * HH * DD * DD];
__device__ __half g_ctxh[BB * HH * DD * DD];
__device__ __half g_qs[(size_t)BB * HH * SS * DD];     // 67 MB  exp(q)^T [bh][n][d]
__device__ __half g_mh[(size_t)BB * SS * CC];          // 67 MB  midT fp16

// ---------------- helpers ----------------
__device__ __forceinline__ uint32_t smem_u32(const void* p) {
    uint32_t a;
    asm("{ .reg .u64 t; cvta.to.shared.u64 t, %1; cvt.u32.u64 %0, t; }" : "=r"(a) : "l"(p));
    return a;
}
#define CP_ASYNC(dst, src) \
    asm volatile("cp.async.cg.shared.global [%0], [%1], 16;" :: "r"(dst), "l"(src) : "memory")
#define CP_COMMIT() asm volatile("cp.async.commit_group;" ::: "memory")
#define CP_WAIT(n)  asm volatile("cp.async.wait_group %0;" :: "n"(n) : "memory")
#define LDSM4(R, addr) \
    asm volatile("ldmatrix.sync.aligned.m8n8.x4.shared.b16 {%0,%1,%2,%3}, [%4];" \
        : "=r"((R)[0]), "=r"((R)[1]), "=r"((R)[2]), "=r"((R)[3]) : "r"(addr))

__device__ __forceinline__ void mma16(float* c, const uint32_t* a, const uint32_t* b) {
    asm volatile(
        "mma.sync.aligned.m16n8k16.row.col.f32.f16.f16.f32 "
        "{%0,%1,%2,%3},{%4,%5,%6,%7},{%8,%9},{%0,%1,%2,%3};"
        : "+f"(c[0]), "+f"(c[1]), "+f"(c[2]), "+f"(c[3])
        : "r"(a[0]), "r"(a[1]), "r"(a[2]), "r"(a[3]), "r"(b[0]), "r"(b[1]));
}

// ---------------------------------------------------------------------------
__global__ void k_prep_wq(const float* __restrict__ w, const float* __restrict__ g1) {
    int i = blockIdx.x * 256 + threadIdx.x;
    g_wqh[i] = __float2half_rn(w[i] * g1[i & (CC - 1)]);
}
__global__ void k_prep_wo(const float* __restrict__ w) {
    int i = blockIdx.x * 256 + threadIdx.x;
    g_woh[i] = __float2half_rn(w[i]);
}

// ---------------------------------------------------------------------------
// normT: xh[b][s][c] = fp16(x[b][c][s]*r[b,s])
// ---------------------------------------------------------------------------
__global__ void k_normT(const float* __restrict__ x) {
    extern __shared__ float sm[];
    float* tile = sm;                  // [512][33]
    float* rr = sm + 512 * 33;
    int b = blockIdx.y, s0 = blockIdx.x * 32;
    int t = threadIdx.x;
    const float* xp = x + (size_t)b * CC * SS + s0;

    for (int i = t; i < 512 * 32; i += 256) {
        int c = i >> 5, sl = i & 31;
        tile[c * 33 + sl] = xp[(size_t)c * SS + sl];
    }
    __syncthreads();

    int sl = t >> 3, part = t & 7;
    float acc = 0.f;
    for (int c = part; c < 512; c += 8) {
        float v = tile[c * 33 + sl];
        acc += v * v;
    }
#pragma unroll
    for (int o = 4; o; o >>= 1) acc += __shfl_down_sync(0xFFFFFFFFu, acc, o);
    if (part == 0) rr[sl] = 22.62741699796952f / fmaxf(sqrtf(acc), 1e-12f);
    __syncthreads();

    float rv = rr[sl];
    __half* op = g_xh + ((size_t)b * SS + s0 + sl) * CC;
    for (int c0 = part * 64; c0 < part * 64 + 64; c0 += 8) {
        __half h[8];
#pragma unroll
        for (int j = 0; j < 8; j++) h[j] = __float2half_rn(tile[(c0 + j) * 33 + sl] * rv);
        *(uint4*)(op + c0) = *(uint4*)h;
    }
}

// ---------------------------------------------------------------------------
// K1: qkv GEMM with fused per-section epilogue:
//   m<512   (q): exp + transpose -> g_qs, col sums -> g_qsum
//   m<1024  (k): exp -> g_ekh, row-sum partials -> g_ksump
//   else    (v): plain fp16 -> g_qkvh
// ---------------------------------------------------------------------------
__global__ __launch_bounds__(256, 2)
void k_hgemm() {
    extern __shared__ char smc[];
    uint32_t sbase = smem_u32(smc);

    int tid = threadIdx.x, lane = tid & 31, wid = tid >> 5;
    int b = blockIdx.z, m0 = blockIdx.y * 128, n0 = blockIdx.x * 128;
    const __half* Ab = g_wqh + (size_t)m0 * CC;
    const __half* Bb = g_xh + (size_t)b * SS * CC + (size_t)n0 * CC;

    const int NC = CC / 64;

    auto issue = [&](int kc, int buf) {
        const __half* Asrc = Ab + kc * 64;
        const __half* Bsrc = Bb + kc * 64;
        uint32_t base = sbase + buf * 32768;
#pragma unroll
        for (int it = 0; it < 4; it++) {
            int id = it * 256 + tid;
            int row = id >> 3, j = id & 7;
            uint32_t dst = base + row * 128 + ((j ^ (row & 7)) << 4);
            CP_ASYNC(dst, Asrc + (size_t)row * CC + j * 8);
            CP_ASYNC(dst + 16384, Bsrc + (size_t)row * CC + j * 8);
        }
    };

#pragma unroll
    for (int s = 0; s < NSTG - 1; s++) { issue(s, s); CP_COMMIT(); }

    int wm = (wid >> 2) * 64, wn = (wid & 3) * 32;
    int rA = wm + (lane & 7) + ((lane >> 3) & 1) * 8;
    int cA = (lane >> 4);
    int rB = wn + (lane & 7) + ((lane >> 4) & 1) * 8;
    int cB = (lane >> 3) & 1;
    int swA = rA & 7, swB = rB & 7;

    float acc[4][4][4] = {};

    for (int kc = 0; kc < NC; kc++) {
        CP_WAIT(NSTG - 2);
        __syncthreads();
        if (kc + NSTG - 1 < NC) issue(kc + NSTG - 1, (kc + NSTG - 1) % NSTG);
        CP_COMMIT();
        uint32_t bufA = sbase + (kc % NSTG) * 32768;
        uint32_t bufB = bufA + 16384;
#pragma unroll
        for (int ks = 0; ks < 4; ks++) {
            uint32_t a[4][4], bf[2][4];
            uint32_t kchA = ((uint32_t)(ks * 2 + cA) ^ swA) << 4;
            uint32_t kchB = ((uint32_t)(ks * 2 + cB) ^ swB) << 4;
#pragma unroll
            for (int mi = 0; mi < 4; mi++)
                LDSM4(a[mi], bufA + (rA + mi * 16) * 128 + kchA);
#pragma unroll
            for (int p = 0; p < 2; p++)
                LDSM4(bf[p], bufB + (rB + p * 16) * 128 + kchB);
#pragma unroll
            for (int mi = 0; mi < 4; mi++)
#pragma unroll
                for (int ni = 0; ni < 4; ni++)
                    mma16(acc[mi][ni], a[mi], bf[ni >> 1] + (ni & 1) * 2);
        }
    }

    if (m0 < 512) {
        // ---- q: exp, transpose via smem, col sums ----
        __syncthreads();                       // safe to reuse stage buffers
        __half* qt = (__half*)smc;             // [c 0..127][r 0..127], stride 136
        float cs[8] = {};
#pragma unroll
        for (int mi = 0; mi < 4; mi++) {
#pragma unroll
            for (int ni = 0; ni < 4; ni++) {
                int c = wn + (ni >> 1) * 16 + (ni & 1) * 8 + (lane & 3) * 2;
                int r = wm + mi * 16 + (lane >> 2);
                float e0 = __expf(acc[mi][ni][0]);
                float e1 = __expf(acc[mi][ni][1]);
                float e2 = __expf(acc[mi][ni][2]);
                float e3 = __expf(acc[mi][ni][3]);
                qt[c * 136 + r]           = __float2half_rn(e0);
                qt[(c + 1) * 136 + r]     = __float2half_rn(e1);
                qt[c * 136 + r + 8]       = __float2half_rn(e2);
                qt[(c + 1) * 136 + r + 8] = __float2half_rn(e3);
                cs[ni * 2]     += e0 + e2;
                cs[ni * 2 + 1] += e1 + e3;
            }
        }
#pragma unroll
        for (int j = 0; j < 8; j++)
#pragma unroll
            for (int o = 4; o <= 16; o <<= 1)
                cs[j] += __shfl_xor_sync(0xFFFFFFFFu, cs[j], o);
        int head = (m0 >> 6) + (wid >> 2);
        if ((lane >> 2) == 0) {
            float* qsump = g_qsum + (size_t)(b * HH + head) * SS + n0;
#pragma unroll
            for (int j = 0; j < 8; j++) {
                int c = wn + ((j >> 2) ? 16 : 0) + (((j >> 1) & 1) ? 8 : 0) +
                        (lane & 3) * 2 + (j & 1);
                qsump[c] = cs[j];
            }
        }
        __syncthreads();
        int n = tid >> 1, hh = tid & 1;
        const uint4* src = (const uint4*)(qt + n * 136 + hh * 64);
        __half* dst = g_qs + ((size_t)(b * HH + (m0 >> 6) + hh) * SS + n0 + n) * 64;
#pragma unroll
        for (int j = 0; j < 8; j++) ((uint4*)dst)[j] = src[j];   // FIX: 8 uint4 = 64 halves
    } else if (m0 < 1024) {
        // ---- k: exp store + row-sum partials ----
        float rs[8] = {};
        __half* ekd = g_ekh + (size_t)(b * 512 + m0 - 512) * SS + n0;
#pragma unroll
        for (int mi = 0; mi < 4; mi++) {
            int r = wm + mi * 16 + (lane >> 2);
#pragma unroll
            for (int ni = 0; ni < 4; ni++) {
                int c = wn + (ni >> 1) * 16 + (ni & 1) * 8 + (lane & 3) * 2;
                float e0 = __expf(acc[mi][ni][0]);
                float e1 = __expf(acc[mi][ni][1]);
                float e2 = __expf(acc[mi][ni][2]);
                float e3 = __expf(acc[mi][ni][3]);
                *(__half2*)(ekd + (size_t)r * SS + c) = __floats2half2_rn(e0, e1);
                *(__half2*)(ekd + (size_t)(r + 8) * SS + c) = __floats2half2_rn(e2, e3);
                rs[mi * 2]     += e0 + e1;
                rs[mi * 2 + 1] += e2 + e3;
            }
        }
#pragma unroll
        for (int j = 0; j < 8; j++) {
            rs[j] += __shfl_xor_sync(0xFFFFFFFFu, rs[j], 1);
            rs[j] += __shfl_xor_sync(0xFFFFFFFFu, rs[j], 2);
        }
        if ((lane & 3) == 0) {
            int slot = blockIdx.x * 4 + (wid & 3);
            float* kp = g_ksump[slot] + b * 512 + (m0 - 512) + wm;
#pragma unroll
            for (int j = 0; j < 8; j++)
                kp[(j >> 1) * 16 + (lane >> 2) + (j & 1) * 8] = rs[j];
        }
    } else {
        // ---- v: plain fp16 ----
        __half* Cd = g_qkvh + (size_t)b * QKV * SS;
#pragma unroll
        for (int mi = 0; mi < 4; mi++) {
            int r0 = m0 + wm + mi * 16 + (lane >> 2);
#pragma unroll
            for (int ni = 0; ni < 4; ni++) {
                int c = n0 + wn + (ni >> 1) * 16 + (ni & 1) * 8 + (lane & 3) * 2;
                *(__half2*)(Cd + (size_t)r0 * SS + c) =
                    __floats2half2_rn(acc[mi][ni][0], acc[mi][ni][1]);
                *(__half2*)(Cd + (size_t)(r0 + 8) * SS + c) =
                    __floats2half2_rn(acc[mi][ni][2], acc[mi][ni][3]);
            }
        }
    }
}

// ---------------------------------------------------------------------------
// ksum finish: sum the 128 partial slots
// ---------------------------------------------------------------------------
__global__ void k_ksumf() {
    int i = blockIdx.x * 256 + threadIdx.x;        // 8192
    float s = 0.f;
#pragma unroll 8
    for (int t = 0; t < 128; t++) s += g_ksump[t][i];
    g_ksum[i] = s;
}

// ---------------------------------------------------------------------------
// ctx_mma: partial ctxT[e][d] = sum_{n in seg} v[e,n] * ek[d,n]
// ---------------------------------------------------------------------------
__global__ __launch_bounds__(128, 3)
void k_ctx_mma() {
    extern __shared__ char smc[];
    int seg = blockIdx.x, h = blockIdx.y, b = blockIdx.z;
    int n0 = seg * CSEG;
    const __half* vp = g_qkvh + ((size_t)b * QKV + 1024 + h * 64) * SS + n0;
    const __half* ekp = g_ekh + (size_t)(b * 512 + h * 64) * SS + n0;

    uint32_t sA = smem_u32(smc), sB = sA + 32768;
    int tid = threadIdx.x, lane = tid & 31, wid = tid >> 5;

#pragma unroll
    for (int it = 0; it < 16; it++) {
        int id = it * 128 + tid;
        int row = id >> 5, j = id & 31;
        uint32_t soff = row * 512 + (((uint32_t)(j ^ (row & 7))) << 4);
        CP_ASYNC(sA + soff, vp + (size_t)row * SS + j * 8);
        CP_ASYNC(sB + soff, ekp + (size_t)row * SS + j * 8);
    }
    CP_COMMIT();
    CP_WAIT(0);
    __syncthreads();

    int rA = wid * 16 + (lane & 7) + ((lane >> 3) & 1) * 8;
    int cA = lane >> 4;
    int rB = (lane & 7) + ((lane >> 4) & 1) * 8;
    int cB = (lane >> 3) & 1;
    int swA = rA & 7, swB = rB & 7;

    float acc[8][4] = {};
#pragma unroll
    for (int ks = 0; ks < 16; ks++) {
        uint32_t a[4], bf[4][4];
        LDSM4(a, sA + rA * 512 + (((uint32_t)(ks * 2 + cA) ^ swA) << 4));
#pragma unroll
        for (int p = 0; p < 4; p++)
            LDSM4(bf[p], sB + (rB + p * 16) * 512 + (((uint32_t)(ks * 2 + cB) ^ swB) << 4));
#pragma unroll
        for (int p = 0; p < 4; p++)
#pragma unroll
            for (int hf = 0; hf < 2; hf++)
                mma16(acc[p * 2 + hf], a, bf[p] + hf * 2);
    }

    float* cp = g_ctxp[seg] + (size_t)(b * HH + h) * 4096;
    int r0 = wid * 16 + (lane >> 2);
#pragma unroll
    for (int ni = 0; ni < 8; ni++) {
        int d = (ni >> 1) * 16 + (ni & 1) * 8 + (lane & 3) * 2;
        *(float2*)(cp + r0 * 64 + d) = make_float2(acc[ni][0], acc[ni][1]);
        *(float2*)(cp + (r0 + 8) * 64 + d) = make_float2(acc[ni][2], acc[ni][3]);
    }
}

// ---------------------------------------------------------------------------
// ctx finish: ctxh[bh][e][d] = fp16( 0.125/ksum[d] * sum_seg ctxp )
// ---------------------------------------------------------------------------
__global__ void k_ctx_fin() {
    int i = blockIdx.x * 256 + threadIdx.x;
    int bh = i >> 12, d = i & 63;
    float s = 0.f;
#pragma unroll
    for (int p = 0; p < NSEG; p++) s += g_ctxp[p][i];
    float inv = 0.125f / g_ksum[(bh >> 3) * 512 + (bh & 7) * 64 + d];
    g_ctxh[i] = __float2half_rn(s * inv);
}

// ---------------------------------------------------------------------------
// apply_mma: mh[b][n][h*64+e] = (1/qsum[n]) * sum_d eq[bh][n][d] * ctxh[bh][e][d]
// ---------------------------------------------------------------------------
__global__ __launch_bounds__(256, 2)
void k_apply_mma() {
    __shared__ __align__(16) char smc[24576];
    int nt = blockIdx.x, h = blockIdx.y, b = blockIdx.z;
    int n0 = nt * 128;
    const __half* Aq = g_qs + ((size_t)(b * HH + h) * SS + n0) * 64;
    const __half* Bc = g_ctxh + (size_t)(b * HH + h) * 4096;
    const float* qsp = g_qsum + (size_t)(b * HH + h) * SS + n0;

    uint32_t sA = smem_u32(smc), sB = sA + 16384;
    int tid = threadIdx.x, lane = tid & 31, wid = tid >> 5;

#pragma unroll
    for (int it = 0; it < 4; it++) {
        int id = it * 256 + tid;
        int row = id >> 3, j = id & 7;
        CP_ASYNC(sA + row * 128 + ((uint32_t)(j ^ (row & 7)) << 4),
                 Aq + (size_t)row * 64 + j * 8);
    }
#pragma unroll
    for (int it = 0; it < 2; it++) {
        int id = it * 256 + tid;
        int row = id >> 3, j = id & 7;
        CP_ASYNC(sB + row * 128 + ((uint32_t)(j ^ (row & 7)) << 4),
                 Bc + (size_t)row * 64 + j * 8);
    }
    CP_COMMIT();
    CP_WAIT(0);
    __syncthreads();

    int wm = (wid >> 1) * 32, wn = (wid & 1) * 32;
    int rA = wm + (lane & 7) + ((lane >> 3) & 1) * 8;
    int cA = lane >> 4;
    int rB = wn + (lane & 7) + ((lane >> 4) & 1) * 8;
    int cB = (lane >> 3) & 1;
    int swA = rA & 7, swB = rB & 7;

    float acc[2][4][4] = {};
#pragma unroll
    for (int ks = 0; ks < 4; ks++) {
        uint32_t a[2][4], bf[2][4];
        uint32_t kchA = ((uint32_t)(ks * 2 + cA) ^ swA) << 4;
        uint32_t kchB = ((uint32_t)(ks * 2 + cB) ^ swB) << 4;
#pragma unroll
        for (int mi = 0; mi < 2; mi++)
            LDSM4(a[mi], sA + (rA + mi * 16) * 128 + kchA);
#pragma unroll
        for (int p = 0; p < 2; p++)
            LDSM4(bf[p], sB + (rB + p * 16) * 128 + kchB);
#pragma unroll
        for (int mi = 0; mi < 2; mi++)
#pragma unroll
            for (int ni = 0; ni < 4; ni++)
                mma16(acc[mi][ni], a[mi], bf[ni >> 1] + (ni & 1) * 2);
    }

    __half* outp = g_mh + (size_t)b * SS * CC;
#pragma unroll
    for (int mi = 0; mi < 2; mi++) {
        int rl = wm + mi * 16 + (lane >> 2);
        float i0 = 1.f / qsp[rl];
        float i1 = 1.f / qsp[rl + 8];
        int r = n0 + rl;
#pragma unroll
        for (int ni = 0; ni < 4; ni++) {
            int c = h * 64 + wn + (ni >> 1) * 16 + (ni & 1) * 8 + (lane & 3) * 2;
            *(__half2*)(outp + (size_t)r * CC + c) =
                __floats2half2_rn(acc[mi][ni][0] * i0, acc[mi][ni][1] * i0);
            *(__half2*)(outp + (size_t)(r + 8) * CC + c) =
                __floats2half2_rn(acc[mi][ni][2] * i1, acc[mi][ni][3] * i1);
        }
    }
}

// ---------------------------------------------------------------------------
// K5: out = rmsnorm( wo @ mh^T + bias ) * gamma2
// ---------------------------------------------------------------------------
__global__ __launch_bounds__(512, 1)
void k_ogemm(const __half* __restrict__ A, const __half* __restrict__ Bg,
             float* __restrict__ out, const float* __restrict__ bias,
             const float* __restrict__ gamma2) {
    extern __shared__ char smc[];
    const int STG = 36864;
    uint32_t sbase = smem_u32(smc);
    float* colsq = (float*)(smc + 3 * STG);
    float* csc   = colsq + 64;

    int tid = threadIdx.x, lane = tid & 31, wid = tid >> 5;
    int b = blockIdx.y, n0 = blockIdx.x * 64;
    const __half* Bb = Bg + ((size_t)b * SS + n0) * CC;

    if (tid < 64) colsq[tid] = 0.f;

    auto issue = [&](int kc, int buf) {
        uint32_t base = sbase + buf * STG;
#pragma unroll
        for (int it = 0; it < 4; it++) {
            int id = it * 512 + tid;
            int row = id >> 2, j = id & 3;
            uint32_t dst = base + row * 64 + (((uint32_t)j ^ ((row >> 1) & 3)) << 4);
            CP_ASYNC(dst, A + (size_t)row * CC + kc * 32 + j * 8);
        }
        if (tid < 256) {
            int row = tid >> 2, j = tid & 3;
            uint32_t dst = base + 32768 + row * 64 + (((uint32_t)j ^ ((row >> 1) & 3)) << 4);
            CP_ASYNC(dst, Bb + (size_t)row * CC + kc * 32 + j * 8);
        }
    };

#pragma unroll
    for (int s = 0; s < NSTG - 1; s++) { issue(s, s); CP_COMMIT(); }

    int wm = (wid >> 1) * 64, wn = (wid & 1) * 32;
    int rA = wm + (lane & 7) + ((lane >> 3) & 1) * 8;
    int cA = (lane >> 4);
    int rB = wn + (lane & 7) + ((lane >> 4) & 1) * 8;
    int cB = (lane >> 3) & 1;
    int swA = (rA >> 1) & 3, swB = (rB >> 1) & 3;

    float acc[4][4][4] = {};
    const int NC = CC / 32;

    for (int kc = 0; kc < NC; kc++) {
        CP_WAIT(NSTG - 2);
        __syncthreads();
        if (kc + NSTG - 1 < NC) issue(kc + NSTG - 1, (kc + NSTG - 1) % NSTG);
        CP_COMMIT();
        uint32_t bufA = sbase + (kc % NSTG) * STG;
        uint32_t bufB = bufA + 32768;
#pragma unroll
        for (int ks = 0; ks < 2; ks++) {
            uint32_t a[4][4], bf[2][4];
            uint32_t kchA = ((uint32_t)(ks * 2 + cA) ^ swA) << 4;
            uint32_t kchB = ((uint32_t)(ks * 2 + cB) ^ swB) << 4;
#pragma unroll
            for (int mi = 0; mi < 4; mi++)
                LDSM4(a[mi], bufA + (rA + mi * 16) * 64 + kchA);
#pragma unroll
            for (int p = 0; p < 2; p++)
                LDSM4(bf[p], bufB + (rB + p * 16) * 64 + kchB);
#pragma unroll
            for (int mi = 0; mi < 4; mi++)
#pragma unroll
                for (int ni = 0; ni < 4; ni++)
                    mma16(acc[mi][ni], a[mi], bf[ni >> 1] + (ni & 1) * 2);
        }
    }

    float bi0[4], bi1[4];
#pragma unroll
    for (int mi = 0; mi < 4; mi++) {
        bi0[mi] = bias[wm + mi * 16 + (lane >> 2)];
        bi1[mi] = bias[wm + mi * 16 + (lane >> 2) + 8];
    }
#pragma unroll
    for (int ni = 0; ni < 4; ni++) {
        float l0 = 0.f, l1 = 0.f;
#pragma unroll
        for (int mi = 0; mi < 4; mi++) {
            acc[mi][ni][0] += bi0[mi]; acc[mi][ni][1] += bi0[mi];
            acc[mi][ni][2] += bi1[mi]; acc[mi][ni][3] += bi1[mi];
            l0 += acc[mi][ni][0] * acc[mi][ni][0] + acc[mi][ni][2] * acc[mi][ni][2];
            l1 += acc[mi][ni][1] * acc[mi][ni][1] + acc[mi][ni][3] * acc[mi][ni][3];
        }
#pragma unroll
        for (int o = 4; o <= 16; o <<= 1) {
            l0 += __shfl_xor_sync(0xFFFFFFFFu, l0, o);
            l1 += __shfl_xor_sync(0xFFFFFFFFu, l1, o);
        }
        if ((lane >> 2) == 0) {
            int cloc = wn + (ni >> 1) * 16 + (ni & 1) * 8 + (lane & 3) * 2;
            atomicAdd(colsq + cloc, l0);
            atomicAdd(colsq + cloc + 1, l1);
        }
    }
    __syncthreads();
    if (tid < 64)
        csc[tid] = 22.62741699796952f / fmaxf(sqrtf(colsq[tid]), 1e-12f);
    __syncthreads();

    float* Cd = out + (size_t)b * CC * SS + n0;
#pragma unroll
    for (int mi = 0; mi < 4; mi++) {
        int r0 = wm + mi * 16 + (lane >> 2);
        float g0 = gamma2[r0], g1 = gamma2[r0 + 8];
#pragma unroll
        for (int ni = 0; ni < 4; ni++) {
            int cloc = wn + (ni >> 1) * 16 + (ni & 1) * 8 + (lane & 3) * 2;
            float s0 = csc[cloc], s1 = csc[cloc + 1];
            *(float2*)(Cd + (size_t)r0 * SS + cloc) =
                make_float2(acc[mi][ni][0] * s0 * g0, acc[mi][ni][1] * s1 * g0);
            *(float2*)(Cd + (size_t)(r0 + 8) * SS + cloc) =
                make_float2(acc[mi][ni][2] * s0 * g1, acc[mi][ni][3] * s1 * g1);
        }
    }
}

// ---------------------------------------------------------------------------
extern "C" void kernel_launch(void* const* d_in, const int* in_sizes, int n_in,
                              void* d_out, int out_size) {
    const float* x      = (const float*)d_in[0];
    const float* gamma1 = (const float*)d_in[1];
    const float* w_qkv  = (const float*)d_in[2];
    const float* w_out  = (const float*)d_in[3];
    const float* b_out  = (const float*)d_in[4];
    const float* gamma2 = (const float*)d_in[5];
    float* out = (float*)d_out;

    __half *woh_p, *mh_p;
    cudaGetSymbolAddress((void**)&woh_p, g_woh);
    cudaGetSymbolAddress((void**)&mh_p,  g_mh);

    const int SMEM_NT = (512 * 33 + 32) * 4;
    const int SMEM_G1 = NSTG * 32768;
    const int SMEM_CX = 65536;
    const int SMEM_G5 = NSTG * 36864 + 512;
    cudaFuncSetAttribute(k_normT,   cudaFuncAttributeMaxDynamicSharedMemorySize, SMEM_NT);
    cudaFuncSetAttribute(k_hgemm,   cudaFuncAttributeMaxDynamicSharedMemorySize, SMEM_G1);
    cudaFuncSetAttribute(k_ctx_mma, cudaFuncAttributeMaxDynamicSharedMemorySize, SMEM_CX);
    cudaFuncSetAttribute(k_ogemm,   cudaFuncAttributeMaxDynamicSharedMemorySize, SMEM_G5);

    k_prep_wq<<<QKV * CC / 256, 256>>>(w_qkv, gamma1);
    k_prep_wo<<<CC * CC / 256, 256>>>(w_out);
    k_normT<<<dim3(SS / 32, BB), 256, SMEM_NT>>>(x);
    // K1: qkv GEMM + fused q-softmax-transpose / k-exp / v epilogues
    k_hgemm<<<dim3(SS / 128, QKV / 128, BB), 256, SMEM_G1>>>();
    // fold k row-sum partials
    k_ksumf<<<BB * 512 / 256, 256>>>();
    // ctx via tensor cores + finish
    k_ctx_mma<<<dim3(NSEG, HH, BB), 128, SMEM_CX>>>();
    k_ctx_fin<<<BB * HH * 4096 / 256, 256>>>();
    // apply exp(q) to ctx, normalize by qsum -> mh
    k_apply_mma<<<dim3(SS / 128, HH, BB), 256>>>();
    // K5: fused out-proj + bias + rms-norm
    k_ogemm<<<dim3(SS / 64, BB), 512, SMEM_G5>>>(woh_p, mh_p, out, b_out, gamma2);
}